// round 1
// baseline (speedup 1.0000x reference)
#include <cuda_runtime.h>
#include <math.h>

#define SEQ 4096
#define EMB 1024
#define OUTD 1024

// Scratch (allocation-free rule: __device__ globals)
__device__ float g_Q[(size_t)SEQ * OUTD];
__device__ float g_K[(size_t)SEQ * OUTD];
__device__ float g_V[(size_t)SEQ * OUTD];
__device__ float g_S[(size_t)SEQ * SEQ];

// ---------------------------------------------------------------------------
// Tiled SGEMM: C[M,N] = alpha * A[M,K] @ op(B)
//   TRANS_B = true : B is [N,K] row-major (C = A * B^T)   -- NT
//   TRANS_B = false: B is [K,N] row-major (C = A * B)     -- NN
// Tile: BM=BN=128, BK=16, 256 threads, 8x8 per thread.
// Requires M%128==0, N%128==0, K%16==0, all pointers 16B aligned.
// ---------------------------------------------------------------------------
template <bool TRANS_B>
__global__ __launch_bounds__(256) void gemm_kernel(
    const float* __restrict__ A, const float* __restrict__ B,
    float* __restrict__ C, int M, int N, int K, float alpha)
{
    __shared__ float As[16][132];   // [k][m], padded
    __shared__ float Bs[16][132];   // [k][n], padded

    const int t  = threadIdx.x;
    const int bx = blockIdx.x;      // N-tile
    const int by = blockIdx.y;      // M-tile
    const int tx = t & 15;          // 0..15 -> n
    const int ty = t >> 4;          // 0..15 -> m

    float acc[8][8];
    #pragma unroll
    for (int i = 0; i < 8; i++)
        #pragma unroll
        for (int j = 0; j < 8; j++) acc[i][j] = 0.0f;

    // A-tile load mapping: 128 rows x 16 cols = 512 float4, 2 per thread
    const int a_row = t >> 2;            // 0..63
    const int a_col = (t & 3) * 4;       // 0,4,8,12
    const float* Ab = A + (size_t)(by * 128) * K;

    // B-tile load mapping
    const float* Bb;
    int b_row, b_col;
    if (TRANS_B) {
        Bb    = B + (size_t)(bx * 128) * K;
        b_row = t >> 2;                  // 0..63 (n)
        b_col = (t & 3) * 4;             // k
    } else {
        Bb    = B + bx * 128;
        b_row = t >> 5;                  // 0..7 (k)
        b_col = (t & 31) * 4;            // n
    }

    for (int k0 = 0; k0 < K; k0 += 16) {
        // ---- load A tile (transposed into smem) ----
        #pragma unroll
        for (int r = 0; r < 2; r++) {
            int row = a_row + r * 64;
            float4 v = *(const float4*)(Ab + (size_t)row * K + k0 + a_col);
            As[a_col + 0][row] = v.x;
            As[a_col + 1][row] = v.y;
            As[a_col + 2][row] = v.z;
            As[a_col + 3][row] = v.w;
        }
        // ---- load B tile ----
        if (TRANS_B) {
            #pragma unroll
            for (int r = 0; r < 2; r++) {
                int row = b_row + r * 64;   // n index
                float4 v = *(const float4*)(Bb + (size_t)row * K + k0 + b_col);
                Bs[b_col + 0][row] = v.x;
                Bs[b_col + 1][row] = v.y;
                Bs[b_col + 2][row] = v.z;
                Bs[b_col + 3][row] = v.w;
            }
        } else {
            #pragma unroll
            for (int r = 0; r < 2; r++) {
                int row = b_row + r * 8;    // k index
                float4 v = *(const float4*)(Bb + (size_t)(k0 + row) * N + b_col);
                *(float4*)&Bs[row][b_col] = v;
            }
        }
        __syncthreads();

        // ---- 128x128x16 compute ----
        #pragma unroll
        for (int kk = 0; kk < 16; kk++) {
            float areg[8], breg[8];
            #pragma unroll
            for (int i = 0; i < 8; i++) areg[i] = As[kk][ty * 8 + i];
            #pragma unroll
            for (int j = 0; j < 8; j++) breg[j] = Bs[kk][tx * 8 + j];
            #pragma unroll
            for (int i = 0; i < 8; i++)
                #pragma unroll
                for (int j = 0; j < 8; j++)
                    acc[i][j] = fmaf(areg[i], breg[j], acc[i][j]);
        }
        __syncthreads();
    }

    // ---- epilogue ----
    #pragma unroll
    for (int i = 0; i < 8; i++) {
        int row = by * 128 + ty * 8 + i;
        float* Cr = C + (size_t)row * N + bx * 128 + tx * 8;
        #pragma unroll
        for (int j = 0; j < 8; j += 4) {
            float4 v;
            v.x = acc[i][j + 0] * alpha;
            v.y = acc[i][j + 1] * alpha;
            v.z = acc[i][j + 2] * alpha;
            v.w = acc[i][j + 3] * alpha;
            *(float4*)(Cr + j) = v;
        }
    }
}

// ---------------------------------------------------------------------------
// Row softmax over S[4096][4096], in place. One CTA (256 thr) per row; each
// thread keeps 16 values (4 float4) in registers: single global read + write.
// ---------------------------------------------------------------------------
__global__ __launch_bounds__(256) void softmax_kernel(float* __restrict__ S)
{
    __shared__ float red[8];
    const int row = blockIdx.x;
    const int t   = threadIdx.x;
    float* p = S + (size_t)row * SEQ;

    float4 v[4];
    #pragma unroll
    for (int i = 0; i < 4; i++)
        v[i] = *(const float4*)(p + 4 * (t + 256 * i));

    // --- max ---
    float mx = -INFINITY;
    #pragma unroll
    for (int i = 0; i < 4; i++) {
        mx = fmaxf(mx, fmaxf(fmaxf(v[i].x, v[i].y), fmaxf(v[i].z, v[i].w)));
    }
    #pragma unroll
    for (int o = 16; o > 0; o >>= 1)
        mx = fmaxf(mx, __shfl_xor_sync(0xFFFFFFFFu, mx, o));
    if ((t & 31) == 0) red[t >> 5] = mx;
    __syncthreads();
    {
        float m = red[t & 7];
        #pragma unroll
        for (int o = 4; o > 0; o >>= 1)
            m = fmaxf(m, __shfl_xor_sync(0xFFFFFFFFu, m, o));
        mx = m;
    }
    __syncthreads();

    // --- exp + sum ---
    float sum = 0.0f;
    #pragma unroll
    for (int i = 0; i < 4; i++) {
        v[i].x = expf(v[i].x - mx); v[i].y = expf(v[i].y - mx);
        v[i].z = expf(v[i].z - mx); v[i].w = expf(v[i].w - mx);
        sum += v[i].x + v[i].y + v[i].z + v[i].w;
    }
    #pragma unroll
    for (int o = 16; o > 0; o >>= 1)
        sum += __shfl_xor_sync(0xFFFFFFFFu, sum, o);
    if ((t & 31) == 0) red[t >> 5] = sum;
    __syncthreads();
    {
        float s = red[t & 7];
        #pragma unroll
        for (int o = 4; o > 0; o >>= 1)
            s += __shfl_xor_sync(0xFFFFFFFFu, s, o);
        sum = s;
    }

    const float inv = 1.0f / sum;
    #pragma unroll
    for (int i = 0; i < 4; i++) {
        v[i].x *= inv; v[i].y *= inv; v[i].z *= inv; v[i].w *= inv;
        *(float4*)(p + 4 * (t + 256 * i)) = v[i];
    }
}

// ---------------------------------------------------------------------------
extern "C" void kernel_launch(void* const* d_in, const int* in_sizes, int n_in,
                              void* d_out, int out_size)
{
    (void)in_sizes; (void)n_in; (void)out_size;
    const float* X  = (const float*)d_in[0];   // (4096, 1024)
    const float* WQ = (const float*)d_in[1];   // (1024, 1024) row-major (out,in)
    const float* WK = (const float*)d_in[2];
    const float* WV = (const float*)d_in[3];
    float* O = (float*)d_out;                  // (4096, 1024)

    float* Q; cudaGetSymbolAddress((void**)&Q, g_Q);
    float* K; cudaGetSymbolAddress((void**)&K, g_K);
    float* V; cudaGetSymbolAddress((void**)&V, g_V);
    float* S; cudaGetSymbolAddress((void**)&S, g_S);

    dim3 thr(256);

    // QKV projections: (4096,1024) = X (4096,1024) @ W^T (1024,1024)
    dim3 gproj(OUTD / 128, SEQ / 128);
    gemm_kernel<true><<<gproj, thr>>>(X, WQ, Q, SEQ, OUTD, EMB, 1.0f);
    gemm_kernel<true><<<gproj, thr>>>(X, WK, K, SEQ, OUTD, EMB, 1.0f);
    gemm_kernel<true><<<gproj, thr>>>(X, WV, V, SEQ, OUTD, EMB, 1.0f);

    // Scores: S = (Q @ K^T) / sqrt(1024)
    dim3 gs(SEQ / 128, SEQ / 128);
    gemm_kernel<true><<<gs, thr>>>(Q, K, S, SEQ, SEQ, OUTD, 0.03125f);

    // Row softmax
    softmax_kernel<<<SEQ, thr>>>(S);

    // Output: O = P @ V   (NN)
    dim3 go(OUTD / 128, SEQ / 128);
    gemm_kernel<false><<<go, thr>>>(S, V, O, SEQ, OUTD, SEQ, 1.0f);
}

// round 2
// speedup vs baseline: 1.0010x; 1.0010x over previous
#include <cuda_runtime.h>
#include <math.h>

#define SEQ 4096
#define EMB 1024
#define OUTD 1024

// Scratch (allocation-free rule: __device__ globals)
__device__ float g_Q[(size_t)SEQ * OUTD];
__device__ float g_K[(size_t)SEQ * OUTD];
__device__ float g_V[(size_t)SEQ * OUTD];
__device__ float g_S[(size_t)SEQ * SEQ];

// ---------------------------------------------------------------------------
// Tiled SGEMM: C[M,N] = alpha * A[M,K] @ op(B)
//   TRANS_B = true : B is [N,K] row-major (C = A * B^T)   -- NT
//   TRANS_B = false: B is [K,N] row-major (C = A * B)     -- NN
// Tile: BM=BN=128, BK=16, 256 threads, 8x8 per thread.
// Requires M%128==0, N%128==0, K%16==0, all pointers 16B aligned.
// ---------------------------------------------------------------------------
template <bool TRANS_B>
__global__ __launch_bounds__(256) void gemm_kernel(
    const float* __restrict__ A, const float* __restrict__ B,
    float* __restrict__ C, int M, int N, int K, float alpha)
{
    __shared__ float As[16][132];   // [k][m], padded
    __shared__ float Bs[16][132];   // [k][n], padded

    const int t  = threadIdx.x;
    const int bx = blockIdx.x;      // N-tile
    const int by = blockIdx.y;      // M-tile
    const int tx = t & 15;          // 0..15 -> n
    const int ty = t >> 4;          // 0..15 -> m

    float acc[8][8];
    #pragma unroll
    for (int i = 0; i < 8; i++)
        #pragma unroll
        for (int j = 0; j < 8; j++) acc[i][j] = 0.0f;

    // A-tile load mapping: 128 rows x 16 cols = 512 float4, 2 per thread
    const int a_row = t >> 2;            // 0..63
    const int a_col = (t & 3) * 4;       // 0,4,8,12
    const float* Ab = A + (size_t)(by * 128) * K;

    // B-tile load mapping
    const float* Bb;
    int b_row, b_col;
    if (TRANS_B) {
        Bb    = B + (size_t)(bx * 128) * K;
        b_row = t >> 2;                  // 0..63 (n)
        b_col = (t & 3) * 4;             // k
    } else {
        Bb    = B + bx * 128;
        b_row = t >> 5;                  // 0..7 (k)
        b_col = (t & 31) * 4;            // n
    }

    for (int k0 = 0; k0 < K; k0 += 16) {
        // ---- load A tile (transposed into smem) ----
        #pragma unroll
        for (int r = 0; r < 2; r++) {
            int row = a_row + r * 64;
            float4 v = *(const float4*)(Ab + (size_t)row * K + k0 + a_col);
            As[a_col + 0][row] = v.x;
            As[a_col + 1][row] = v.y;
            As[a_col + 2][row] = v.z;
            As[a_col + 3][row] = v.w;
        }
        // ---- load B tile ----
        if (TRANS_B) {
            #pragma unroll
            for (int r = 0; r < 2; r++) {
                int row = b_row + r * 64;   // n index
                float4 v = *(const float4*)(Bb + (size_t)row * K + k0 + b_col);
                Bs[b_col + 0][row] = v.x;
                Bs[b_col + 1][row] = v.y;
                Bs[b_col + 2][row] = v.z;
                Bs[b_col + 3][row] = v.w;
            }
        } else {
            #pragma unroll
            for (int r = 0; r < 2; r++) {
                int row = b_row + r * 8;    // k index
                float4 v = *(const float4*)(Bb + (size_t)(k0 + row) * N + b_col);
                *(float4*)&Bs[row][b_col] = v;
            }
        }
        __syncthreads();

        // ---- 128x128x16 compute ----
        #pragma unroll
        for (int kk = 0; kk < 16; kk++) {
            float areg[8], breg[8];
            #pragma unroll
            for (int i = 0; i < 8; i++) areg[i] = As[kk][ty * 8 + i];
            #pragma unroll
            for (int j = 0; j < 8; j++) breg[j] = Bs[kk][tx * 8 + j];
            #pragma unroll
            for (int i = 0; i < 8; i++)
                #pragma unroll
                for (int j = 0; j < 8; j++)
                    acc[i][j] = fmaf(areg[i], breg[j], acc[i][j]);
        }
        __syncthreads();
    }

    // ---- epilogue ----
    #pragma unroll
    for (int i = 0; i < 8; i++) {
        int row = by * 128 + ty * 8 + i;
        float* Cr = C + (size_t)row * N + bx * 128 + tx * 8;
        #pragma unroll
        for (int j = 0; j < 8; j += 4) {
            float4 v;
            v.x = acc[i][j + 0] * alpha;
            v.y = acc[i][j + 1] * alpha;
            v.z = acc[i][j + 2] * alpha;
            v.w = acc[i][j + 3] * alpha;
            *(float4*)(Cr + j) = v;
        }
    }
}

// ---------------------------------------------------------------------------
// Row softmax over S[4096][4096], in place. One CTA (256 thr) per row; each
// thread keeps 16 values (4 float4) in registers: single global read + write.
// ---------------------------------------------------------------------------
__global__ __launch_bounds__(256) void softmax_kernel(float* __restrict__ S)
{
    __shared__ float red[8];
    const int row = blockIdx.x;
    const int t   = threadIdx.x;
    float* p = S + (size_t)row * SEQ;

    float4 v[4];
    #pragma unroll
    for (int i = 0; i < 4; i++)
        v[i] = *(const float4*)(p + 4 * (t + 256 * i));

    // --- max ---
    float mx = -INFINITY;
    #pragma unroll
    for (int i = 0; i < 4; i++) {
        mx = fmaxf(mx, fmaxf(fmaxf(v[i].x, v[i].y), fmaxf(v[i].z, v[i].w)));
    }
    #pragma unroll
    for (int o = 16; o > 0; o >>= 1)
        mx = fmaxf(mx, __shfl_xor_sync(0xFFFFFFFFu, mx, o));
    if ((t & 31) == 0) red[t >> 5] = mx;
    __syncthreads();
    {
        float m = red[t & 7];
        #pragma unroll
        for (int o = 4; o > 0; o >>= 1)
            m = fmaxf(m, __shfl_xor_sync(0xFFFFFFFFu, m, o));
        mx = m;
    }
    __syncthreads();

    // --- exp + sum ---
    float sum = 0.0f;
    #pragma unroll
    for (int i = 0; i < 4; i++) {
        v[i].x = expf(v[i].x - mx); v[i].y = expf(v[i].y - mx);
        v[i].z = expf(v[i].z - mx); v[i].w = expf(v[i].w - mx);
        sum += v[i].x + v[i].y + v[i].z + v[i].w;
    }
    #pragma unroll
    for (int o = 16; o > 0; o >>= 1)
        sum += __shfl_xor_sync(0xFFFFFFFFu, sum, o);
    if ((t & 31) == 0) red[t >> 5] = sum;
    __syncthreads();
    {
        float s = red[t & 7];
        #pragma unroll
        for (int o = 4; o > 0; o >>= 1)
            s += __shfl_xor_sync(0xFFFFFFFFu, s, o);
        sum = s;
    }

    const float inv = 1.0f / sum;
    #pragma unroll
    for (int i = 0; i < 4; i++) {
        v[i].x *= inv; v[i].y *= inv; v[i].z *= inv; v[i].w *= inv;
        *(float4*)(p + 4 * (t + 256 * i)) = v[i];
    }
}

// ---------------------------------------------------------------------------
extern "C" void kernel_launch(void* const* d_in, const int* in_sizes, int n_in,
                              void* d_out, int out_size)
{
    (void)in_sizes; (void)n_in; (void)out_size;
    const float* X  = (const float*)d_in[0];   // (4096, 1024)
    const float* WQ = (const float*)d_in[1];   // (1024, 1024) row-major (out,in)
    const float* WK = (const float*)d_in[2];
    const float* WV = (const float*)d_in[3];
    float* O = (float*)d_out;                  // (4096, 1024)

    float* Q; cudaGetSymbolAddress((void**)&Q, g_Q);
    float* K; cudaGetSymbolAddress((void**)&K, g_K);
    float* V; cudaGetSymbolAddress((void**)&V, g_V);
    float* S; cudaGetSymbolAddress((void**)&S, g_S);

    dim3 thr(256);

    // QKV projections: (4096,1024) = X (4096,1024) @ W^T (1024,1024)
    dim3 gproj(OUTD / 128, SEQ / 128);
    gemm_kernel<true><<<gproj, thr>>>(X, WQ, Q, SEQ, OUTD, EMB, 1.0f);
    gemm_kernel<true><<<gproj, thr>>>(X, WK, K, SEQ, OUTD, EMB, 1.0f);
    gemm_kernel<true><<<gproj, thr>>>(X, WV, V, SEQ, OUTD, EMB, 1.0f);

    // Scores: S = (Q @ K^T) / sqrt(1024)
    dim3 gs(SEQ / 128, SEQ / 128);
    gemm_kernel<true><<<gs, thr>>>(Q, K, S, SEQ, SEQ, OUTD, 0.03125f);

    // Row softmax
    softmax_kernel<<<SEQ, thr>>>(S);

    // Output: O = P @ V   (NN)
    dim3 go(OUTD / 128, SEQ / 128);
    gemm_kernel<false><<<go, thr>>>(S, V, O, SEQ, OUTD, SEQ, 1.0f);
}

// round 5
// speedup vs baseline: 1.6341x; 1.6325x over previous
#include <cuda_runtime.h>
#include <cuda_bf16.h>
#include <stdint.h>
#include <stddef.h>
#include <math.h>

#define SEQ 4096
#define EMB 1024
#define OUTD 1024

// ---------------- scratch (__device__ globals; allocation-free rule) -------
__device__ __nv_bfloat16 g_Xh[(size_t)SEQ * EMB],  g_Xl[(size_t)SEQ * EMB];
__device__ __nv_bfloat16 g_WQh[(size_t)OUTD * EMB], g_WQl[(size_t)OUTD * EMB];
__device__ __nv_bfloat16 g_WKh[(size_t)OUTD * EMB], g_WKl[(size_t)OUTD * EMB];
__device__ __nv_bfloat16 g_WVh[(size_t)OUTD * EMB], g_WVl[(size_t)OUTD * EMB];
__device__ __nv_bfloat16 g_Qh[(size_t)SEQ * OUTD],  g_Ql[(size_t)SEQ * OUTD];
__device__ __nv_bfloat16 g_Kh[(size_t)SEQ * OUTD],  g_Kl[(size_t)SEQ * OUTD];
__device__ __nv_bfloat16 g_Vth[(size_t)OUTD * SEQ], g_Vtl[(size_t)OUTD * SEQ]; // V^T
__device__ float         g_S[(size_t)SEQ * SEQ];
__device__ __nv_bfloat16 g_Ph[(size_t)SEQ * SEQ],  g_Pl[(size_t)SEQ * SEQ];

// ---------------- PTX helpers (sm_80-class only; NO tcgen05) ---------------
__device__ __forceinline__ uint32_t smem_u32(const void* p) {
    uint32_t a;
    asm("{ .reg .u64 t; cvta.to.shared.u64 t, %1; cvt.u32.u64 %0, t; }"
        : "=r"(a) : "l"(p));
    return a;
}
__device__ __forceinline__ void cp16(uint32_t dst, const void* src) {
    asm volatile("cp.async.cg.shared.global [%0], [%1], 16;" :: "r"(dst), "l"(src));
}
__device__ __forceinline__ void cp_commit() {
    asm volatile("cp.async.commit_group;" ::: "memory");
}
__device__ __forceinline__ void cp_wait2() {
    asm volatile("cp.async.wait_group 2;" ::: "memory");
}
__device__ __forceinline__ void ldsm4(uint32_t& r0, uint32_t& r1, uint32_t& r2,
                                      uint32_t& r3, uint32_t addr) {
    asm volatile("ldmatrix.sync.aligned.m8n8.x4.shared.b16 {%0,%1,%2,%3}, [%4];"
                 : "=r"(r0), "=r"(r1), "=r"(r2), "=r"(r3) : "r"(addr));
}
__device__ __forceinline__ void mma16816(float* c, const uint32_t* a,
                                         const uint32_t* b) {
    asm volatile(
        "mma.sync.aligned.m16n8k16.row.col.f32.bf16.bf16.f32 "
        "{%0,%1,%2,%3}, {%4,%5,%6,%7}, {%8,%9}, {%0,%1,%2,%3};"
        : "+f"(c[0]), "+f"(c[1]), "+f"(c[2]), "+f"(c[3])
        : "r"(a[0]), "r"(a[1]), "r"(a[2]), "r"(a[3]), "r"(b[0]), "r"(b[1]));
}

// ---------------- split-bf16 warp-MMA GEMM ---------------------------------
// C[M,N] = alpha * A[M,K] @ B[N,K]^T, A,B as (hi,lo) bf16 pairs, K-major.
// CTA 128x128, BK=64, 3 cp.async stages, 8 warps (2M x 4N), warp tile 64x32.
// MODE 0: fp32 C. MODE 1: split bf16 Ch/Cl. MODE 2: split bf16 transposed.
#define BM 128
#define BN 128
#define BK 64
#define NSTG 3
#define TILE_BYTES_1 16384                 // one 128x64 bf16 tile (128B rows)
#define STAGE_BYTES  65536                 // Ah, Al, Bh, Bl
#define GEMM_SMEM (NSTG * STAGE_BYTES)

template <int MODE>
__global__ void __launch_bounds__(256, 1) gemm_bf3(
    const __nv_bfloat16* __restrict__ Ah, const __nv_bfloat16* __restrict__ Al,
    const __nv_bfloat16* __restrict__ Bh, const __nv_bfloat16* __restrict__ Bl,
    float* __restrict__ Cf, __nv_bfloat16* __restrict__ Ch,
    __nv_bfloat16* __restrict__ Cl, int K, int ldc, float alpha)
{
    extern __shared__ char smem_raw[];
    const uint32_t TILES = smem_u32(smem_raw);

    const int t    = threadIdx.x;
    const int w    = t >> 5;
    const int lane = t & 31;
    const int m0   = blockIdx.y * BM;
    const int n0   = blockIdx.x * BN;
    const int wm   = w >> 2;               // 0..1
    const int wn   = w & 3;                // 0..3
    const int warp_m = wm * 64;
    const int warp_n = wn * 32;

    float acc[4][4][4];
#pragma unroll
    for (int i = 0; i < 4; i++)
#pragma unroll
        for (int j = 0; j < 4; j++)
#pragma unroll
            for (int kq = 0; kq < 4; kq++) acc[i][j][kq] = 0.0f;

    // ---- cp.async plan: thread t owns tile t>>6, two rows, 8 chunks each --
    const int tsel = t >> 6;                        // 0:Ah 1:Al 2:Bh 3:Bl
    const __nv_bfloat16* tb = (tsel == 0) ? Ah : (tsel == 1) ? Al
                            : (tsel == 2) ? Bh : Bl;
    const int rl0 = (t & 63) * 2;                   // local row in tile
    const int grow0 = ((tsel < 2) ? m0 : n0) + rl0; // global row
    const __nv_bfloat16* src0 = tb + (size_t)grow0 * K;
    const uint32_t dbase = (uint32_t)tsel * TILE_BYTES_1;

    auto load_stage = [&](int s) {
        uint32_t sb = TILES + s * STAGE_BYTES + dbase;
#pragma unroll
        for (int i = 0; i < 16; i++) {
            int rl = rl0 + (i >> 3);
            uint32_t off = (uint32_t)rl * 128 +
                           (((uint32_t)(i & 7) * 16) ^ (((uint32_t)rl & 7) << 4));
            cp16(sb + off, src0 + (size_t)(i >> 3) * K + (i & 7) * 8);
        }
        src0 += BK;
    };

    // ---- ldmatrix address precompute ----
    // A (x4): lanes 0-15 rows m..m+15, lanes 16-31 same rows, +16B col
    uint32_t a_off[4], a_xor[4];
#pragma unroll
    for (int mf = 0; mf < 4; mf++) {
        int rl = warp_m + mf * 16 + (lane & 15);
        a_off[mf] = (uint32_t)rl * 128;
        a_xor[mf] = ((uint32_t)rl & 7) << 4;
    }
    const uint32_t a_bc = ((uint32_t)lane >> 4) * 16;
    // B (x4 covers 2 n-frags): lanes0-7 rows n..n+7 bc0, 8-15 same rows +16B,
    // 16-23 rows+8 bc0, 24-31 rows+8 +16B
    uint32_t b_off[2], b_xor[2];
#pragma unroll
    for (int nfp = 0; nfp < 2; nfp++) {
        int rl = warp_n + nfp * 16 + (lane & 7) + ((lane & 16) ? 8 : 0);
        b_off[nfp] = (uint32_t)rl * 128;
        b_xor[nfp] = ((uint32_t)rl & 7) << 4;
    }
    const uint32_t b_bc = (((uint32_t)lane >> 3) & 1) * 16;

    const int kt = K / BK;

    // prologue
    load_stage(0); cp_commit();
    load_stage(1); cp_commit();

    for (int it = 0; it < kt; it++) {
        const int s = it % NSTG;
        if (it + 2 < kt) load_stage((it + 2) % NSTG);
        cp_commit();
        cp_wait2();
        __syncthreads();

        const uint32_t sb  = TILES + s * STAGE_BYTES;
        const uint32_t sAh = sb;
        const uint32_t sAl = sb + TILE_BYTES_1;
        const uint32_t sBh = sb + 2 * TILE_BYTES_1;
        const uint32_t sBl = sb + 3 * TILE_BYTES_1;

#pragma unroll
        for (int ks = 0; ks < 4; ks++) {
            const uint32_t bcA = (uint32_t)ks * 32 + a_bc;
            const uint32_t bcB = (uint32_t)ks * 32 + b_bc;
            uint32_t ah[4][4], al2[4][4];
#pragma unroll
            for (int mf = 0; mf < 4; mf++) {
                ldsm4(ah[mf][0], ah[mf][1], ah[mf][2], ah[mf][3],
                      sAh + a_off[mf] + (bcA ^ a_xor[mf]));
                ldsm4(al2[mf][0], al2[mf][1], al2[mf][2], al2[mf][3],
                      sAl + a_off[mf] + (bcA ^ a_xor[mf]));
            }
            uint32_t bh[4][2], bl2[4][2];
#pragma unroll
            for (int nfp = 0; nfp < 2; nfp++) {
                uint32_t r0, r1, r2, r3;
                ldsm4(r0, r1, r2, r3, sBh + b_off[nfp] + (bcB ^ b_xor[nfp]));
                bh[2 * nfp][0] = r0; bh[2 * nfp][1] = r1;
                bh[2 * nfp + 1][0] = r2; bh[2 * nfp + 1][1] = r3;
                ldsm4(r0, r1, r2, r3, sBl + b_off[nfp] + (bcB ^ b_xor[nfp]));
                bl2[2 * nfp][0] = r0; bl2[2 * nfp][1] = r1;
                bl2[2 * nfp + 1][0] = r2; bl2[2 * nfp + 1][1] = r3;
            }
#pragma unroll
            for (int mf = 0; mf < 4; mf++)
#pragma unroll
                for (int nf = 0; nf < 4; nf++) {
                    mma16816(acc[mf][nf], ah[mf], bh[nf]);
                    mma16816(acc[mf][nf], ah[mf], bl2[nf]);
                    mma16816(acc[mf][nf], al2[mf], bh[nf]);
                }
        }
        __syncthreads();
    }

    // ---- epilogue: acc frag layout: c0,c1 at (row, col..col+1),
    //      c2,c3 at (row+8, col..col+1)
#pragma unroll
    for (int mf = 0; mf < 4; mf++) {
#pragma unroll
        for (int nf = 0; nf < 4; nf++) {
            int row = m0 + warp_m + mf * 16 + (lane >> 2);
            int col = n0 + warp_n + nf * 8 + (lane & 3) * 2;
            float f00 = acc[mf][nf][0] * alpha;
            float f01 = acc[mf][nf][1] * alpha;
            float f10 = acc[mf][nf][2] * alpha;
            float f11 = acc[mf][nf][3] * alpha;
            if (MODE == 0) {
                *(float2*)(Cf + (size_t)row * ldc + col)       = make_float2(f00, f01);
                *(float2*)(Cf + (size_t)(row + 8) * ldc + col) = make_float2(f10, f11);
            } else if (MODE == 1) {
                __nv_bfloat16 h00 = __float2bfloat16(f00);
                __nv_bfloat16 h01 = __float2bfloat16(f01);
                __nv_bfloat16 h10 = __float2bfloat16(f10);
                __nv_bfloat16 h11 = __float2bfloat16(f11);
                __nv_bfloat16 l00 = __float2bfloat16(f00 - __bfloat162float(h00));
                __nv_bfloat16 l01 = __float2bfloat16(f01 - __bfloat162float(h01));
                __nv_bfloat16 l10 = __float2bfloat16(f10 - __bfloat162float(h10));
                __nv_bfloat16 l11 = __float2bfloat16(f11 - __bfloat162float(h11));
                *(__nv_bfloat162*)(Ch + (size_t)row * ldc + col)       = __halves2bfloat162(h00, h01);
                *(__nv_bfloat162*)(Ch + (size_t)(row + 8) * ldc + col) = __halves2bfloat162(h10, h11);
                *(__nv_bfloat162*)(Cl + (size_t)row * ldc + col)       = __halves2bfloat162(l00, l01);
                *(__nv_bfloat162*)(Cl + (size_t)(row + 8) * ldc + col) = __halves2bfloat162(l10, l11);
            } else { // MODE 2: transposed: C*[col][row], ldc = M_total
                __nv_bfloat16 h00 = __float2bfloat16(f00);
                __nv_bfloat16 h01 = __float2bfloat16(f01);
                __nv_bfloat16 h10 = __float2bfloat16(f10);
                __nv_bfloat16 h11 = __float2bfloat16(f11);
                Ch[(size_t)col * ldc + row]           = h00;
                Ch[(size_t)(col + 1) * ldc + row]     = h01;
                Ch[(size_t)col * ldc + row + 8]       = h10;
                Ch[(size_t)(col + 1) * ldc + row + 8] = h11;
                Cl[(size_t)col * ldc + row]           = __float2bfloat16(f00 - __bfloat162float(h00));
                Cl[(size_t)(col + 1) * ldc + row]     = __float2bfloat16(f01 - __bfloat162float(h01));
                Cl[(size_t)col * ldc + row + 8]       = __float2bfloat16(f10 - __bfloat162float(h10));
                Cl[(size_t)(col + 1) * ldc + row + 8] = __float2bfloat16(f11 - __bfloat162float(h11));
            }
        }
    }
}

// ---------------- fp32 -> (hi,lo) bf16 split --------------------------------
__global__ void __launch_bounds__(256) split_kernel(
    const float* __restrict__ in, __nv_bfloat16* __restrict__ hi,
    __nv_bfloat16* __restrict__ lo, int n4)
{
    int i = blockIdx.x * 256 + threadIdx.x;
    if (i >= n4) return;
    float4 v = ((const float4*)in)[i];
    __nv_bfloat16 h0 = __float2bfloat16(v.x), h1 = __float2bfloat16(v.y);
    __nv_bfloat16 h2 = __float2bfloat16(v.z), h3 = __float2bfloat16(v.w);
    __nv_bfloat16 l0 = __float2bfloat16(v.x - __bfloat162float(h0));
    __nv_bfloat16 l1 = __float2bfloat16(v.y - __bfloat162float(h1));
    __nv_bfloat16 l2 = __float2bfloat16(v.z - __bfloat162float(h2));
    __nv_bfloat16 l3 = __float2bfloat16(v.w - __bfloat162float(h3));
    ((__nv_bfloat162*)hi)[2 * i]     = __halves2bfloat162(h0, h1);
    ((__nv_bfloat162*)hi)[2 * i + 1] = __halves2bfloat162(h2, h3);
    ((__nv_bfloat162*)lo)[2 * i]     = __halves2bfloat162(l0, l1);
    ((__nv_bfloat162*)lo)[2 * i + 1] = __halves2bfloat162(l2, l3);
}

// ---------------- row softmax -> split bf16 P -------------------------------
__global__ void __launch_bounds__(256) softmax_split_kernel(
    const float* __restrict__ S, __nv_bfloat16* __restrict__ Ph,
    __nv_bfloat16* __restrict__ Pl)
{
    __shared__ float red[8];
    const int row = blockIdx.x;
    const int t   = threadIdx.x;
    const float* p = S + (size_t)row * SEQ;

    float4 v[4];
#pragma unroll
    for (int i = 0; i < 4; i++)
        v[i] = *(const float4*)(p + 4 * (t + 256 * i));

    float mx = -INFINITY;
#pragma unroll
    for (int i = 0; i < 4; i++)
        mx = fmaxf(mx, fmaxf(fmaxf(v[i].x, v[i].y), fmaxf(v[i].z, v[i].w)));
#pragma unroll
    for (int o = 16; o > 0; o >>= 1)
        mx = fmaxf(mx, __shfl_xor_sync(0xFFFFFFFFu, mx, o));
    if ((t & 31) == 0) red[t >> 5] = mx;
    __syncthreads();
    {
        float m = red[t & 7];
#pragma unroll
        for (int o = 4; o > 0; o >>= 1)
            m = fmaxf(m, __shfl_xor_sync(0xFFFFFFFFu, m, o));
        mx = m;
    }
    __syncthreads();

    float sum = 0.0f;
#pragma unroll
    for (int i = 0; i < 4; i++) {
        v[i].x = expf(v[i].x - mx); v[i].y = expf(v[i].y - mx);
        v[i].z = expf(v[i].z - mx); v[i].w = expf(v[i].w - mx);
        sum += v[i].x + v[i].y + v[i].z + v[i].w;
    }
#pragma unroll
    for (int o = 16; o > 0; o >>= 1)
        sum += __shfl_xor_sync(0xFFFFFFFFu, sum, o);
    if ((t & 31) == 0) red[t >> 5] = sum;
    __syncthreads();
    {
        float s2 = red[t & 7];
#pragma unroll
        for (int o = 4; o > 0; o >>= 1)
            s2 += __shfl_xor_sync(0xFFFFFFFFu, s2, o);
        sum = s2;
    }

    const float inv = 1.0f / sum;
#pragma unroll
    for (int i = 0; i < 4; i++) {
        size_t idx = (size_t)row * SEQ + 4 * (t + 256 * i);
        float f0 = v[i].x * inv, f1 = v[i].y * inv;
        float f2 = v[i].z * inv, f3 = v[i].w * inv;
        __nv_bfloat16 h0 = __float2bfloat16(f0), h1 = __float2bfloat16(f1);
        __nv_bfloat16 h2 = __float2bfloat16(f2), h3 = __float2bfloat16(f3);
        __nv_bfloat16 l0 = __float2bfloat16(f0 - __bfloat162float(h0));
        __nv_bfloat16 l1 = __float2bfloat16(f1 - __bfloat162float(h1));
        __nv_bfloat16 l2 = __float2bfloat16(f2 - __bfloat162float(h2));
        __nv_bfloat16 l3 = __float2bfloat16(f3 - __bfloat162float(h3));
        *(__nv_bfloat162*)(Ph + idx)     = __halves2bfloat162(h0, h1);
        *(__nv_bfloat162*)(Ph + idx + 2) = __halves2bfloat162(h2, h3);
        *(__nv_bfloat162*)(Pl + idx)     = __halves2bfloat162(l0, l1);
        *(__nv_bfloat162*)(Pl + idx + 2) = __halves2bfloat162(l2, l3);
    }
}

// ---------------------------------------------------------------------------
extern "C" void kernel_launch(void* const* d_in, const int* in_sizes, int n_in,
                              void* d_out, int out_size)
{
    (void)in_sizes; (void)n_in; (void)out_size;
    const float* X  = (const float*)d_in[0];
    const float* WQ = (const float*)d_in[1];
    const float* WK = (const float*)d_in[2];
    const float* WV = (const float*)d_in[3];
    float* O = (float*)d_out;

    __nv_bfloat16 *Xh, *Xl, *WQh, *WQl, *WKh, *WKl, *WVh, *WVl;
    __nv_bfloat16 *Qh, *Ql, *Kh, *Kl, *Vth, *Vtl, *Ph, *Pl;
    float* S;
    cudaGetSymbolAddress((void**)&Xh, g_Xh);   cudaGetSymbolAddress((void**)&Xl, g_Xl);
    cudaGetSymbolAddress((void**)&WQh, g_WQh); cudaGetSymbolAddress((void**)&WQl, g_WQl);
    cudaGetSymbolAddress((void**)&WKh, g_WKh); cudaGetSymbolAddress((void**)&WKl, g_WKl);
    cudaGetSymbolAddress((void**)&WVh, g_WVh); cudaGetSymbolAddress((void**)&WVl, g_WVl);
    cudaGetSymbolAddress((void**)&Qh, g_Qh);   cudaGetSymbolAddress((void**)&Ql, g_Ql);
    cudaGetSymbolAddress((void**)&Kh, g_Kh);   cudaGetSymbolAddress((void**)&Kl, g_Kl);
    cudaGetSymbolAddress((void**)&Vth, g_Vth); cudaGetSymbolAddress((void**)&Vtl, g_Vtl);
    cudaGetSymbolAddress((void**)&Ph, g_Ph);   cudaGetSymbolAddress((void**)&Pl, g_Pl);
    cudaGetSymbolAddress((void**)&S, g_S);

    cudaFuncSetAttribute(gemm_bf3<0>, cudaFuncAttributeMaxDynamicSharedMemorySize, GEMM_SMEM);
    cudaFuncSetAttribute(gemm_bf3<1>, cudaFuncAttributeMaxDynamicSharedMemorySize, GEMM_SMEM);
    cudaFuncSetAttribute(gemm_bf3<2>, cudaFuncAttributeMaxDynamicSharedMemorySize, GEMM_SMEM);

    // 1) split inputs to (hi, lo) bf16
    {
        int n4 = SEQ * EMB / 4;
        split_kernel<<<(n4 + 255) / 256, 256>>>(X, Xh, Xl, n4);
        int w4 = OUTD * EMB / 4;
        split_kernel<<<(w4 + 255) / 256, 256>>>(WQ, WQh, WQl, w4);
        split_kernel<<<(w4 + 255) / 256, 256>>>(WK, WKh, WKl, w4);
        split_kernel<<<(w4 + 255) / 256, 256>>>(WV, WVh, WVl, w4);
    }

    dim3 thr(256);

    // 2) projections (NT): Q,K split-bf16 out; V split + transposed
    dim3 gp(OUTD / BN, SEQ / BM);
    gemm_bf3<1><<<gp, thr, GEMM_SMEM>>>(Xh, Xl, WQh, WQl, nullptr, Qh, Ql, EMB, OUTD, 1.0f);
    gemm_bf3<1><<<gp, thr, GEMM_SMEM>>>(Xh, Xl, WKh, WKl, nullptr, Kh, Kl, EMB, OUTD, 1.0f);
    gemm_bf3<2><<<gp, thr, GEMM_SMEM>>>(Xh, Xl, WVh, WVl, nullptr, Vth, Vtl, EMB, SEQ, 1.0f);

    // 3) scores: S = (Q @ K^T) / 32  (fp32 out)
    dim3 gs(SEQ / BN, SEQ / BM);
    gemm_bf3<0><<<gs, thr, GEMM_SMEM>>>(Qh, Ql, Kh, Kl, S, nullptr, nullptr, OUTD, SEQ, 0.03125f);

    // 4) softmax -> split bf16 P
    softmax_split_kernel<<<SEQ, thr>>>(S, Ph, Pl);

    // 5) O = P @ V = P @ (V^T)^T (NT with B = V^T)
    dim3 go(OUTD / BN, SEQ / BM);
    gemm_bf3<0><<<go, thr, GEMM_SMEM>>>(Ph, Pl, Vth, Vtl, O, nullptr, nullptr, SEQ, OUTD, 1.0f);
}

// round 7
// speedup vs baseline: 2.9501x; 1.8053x over previous
#include <cuda_runtime.h>
#include <cuda_bf16.h>
#include <stdint.h>
#include <stddef.h>
#include <math.h>

#define SEQ 4096
#define EMB 1024
#define OUTD 1024

// ---------------- scratch (__device__ globals; allocation-free rule) -------
__device__ __nv_bfloat16 g_Xh[(size_t)SEQ * EMB],  g_Xl[(size_t)SEQ * EMB];
__device__ __nv_bfloat16 g_WQh[(size_t)OUTD * EMB], g_WQl[(size_t)OUTD * EMB];
__device__ __nv_bfloat16 g_WKh[(size_t)OUTD * EMB], g_WKl[(size_t)OUTD * EMB];
__device__ __nv_bfloat16 g_WVh[(size_t)OUTD * EMB], g_WVl[(size_t)OUTD * EMB];
__device__ __nv_bfloat16 g_Qh[(size_t)SEQ * OUTD],  g_Ql[(size_t)SEQ * OUTD];
__device__ __nv_bfloat16 g_Kh[(size_t)SEQ * OUTD],  g_Kl[(size_t)SEQ * OUTD];
__device__ __nv_bfloat16 g_Vth[(size_t)OUTD * SEQ], g_Vtl[(size_t)OUTD * SEQ]; // V^T
__device__ float         g_S[(size_t)SEQ * SEQ];
__device__ __nv_bfloat16 g_Ph[(size_t)SEQ * SEQ],  g_Pl[(size_t)SEQ * SEQ];

// ---------------- PTX helpers (sm_80-class only) ---------------------------
__device__ __forceinline__ uint32_t smem_u32(const void* p) {
    uint32_t a;
    asm("{ .reg .u64 t; cvta.to.shared.u64 t, %1; cvt.u32.u64 %0, t; }"
        : "=r"(a) : "l"(p));
    return a;
}
__device__ __forceinline__ void cp16(uint32_t dst, const void* src) {
    asm volatile("cp.async.cg.shared.global [%0], [%1], 16;" :: "r"(dst), "l"(src));
}
__device__ __forceinline__ void cp_commit() {
    asm volatile("cp.async.commit_group;" ::: "memory");
}
__device__ __forceinline__ void cp_wait1() {
    asm volatile("cp.async.wait_group 1;" ::: "memory");
}
__device__ __forceinline__ void ldsm4(uint32_t& r0, uint32_t& r1, uint32_t& r2,
                                      uint32_t& r3, uint32_t addr) {
    asm volatile("ldmatrix.sync.aligned.m8n8.x4.shared.b16 {%0,%1,%2,%3}, [%4];"
                 : "=r"(r0), "=r"(r1), "=r"(r2), "=r"(r3) : "r"(addr));
}
__device__ __forceinline__ void mma16816(float* c, const uint32_t* a,
                                         const uint32_t* b) {
    asm volatile(
        "mma.sync.aligned.m16n8k16.row.col.f32.bf16.bf16.f32 "
        "{%0,%1,%2,%3}, {%4,%5,%6,%7}, {%8,%9}, {%0,%1,%2,%3};"
        : "+f"(c[0]), "+f"(c[1]), "+f"(c[2]), "+f"(c[3])
        : "r"(a[0]), "r"(a[1]), "r"(a[2]), "r"(a[3]), "r"(b[0]), "r"(b[1]));
}

// ---------------- split-bf16 warp-MMA GEMM (3-term) ------------------------
// C[M,N] = alpha * A[M,K] @ B[N,K]^T, K-major rows, A,B as (hi,lo) pairs.
// Terms: Ah*Bh + Ah*Bl + Al*Bh.
// CTA 256x128, BK=64, 2 cp.async stages, 16 warps (4M x 4N), warp tile 64x32.
// MODE 0: fp32 C. MODE 1: split bf16 Ch/Cl. MODE 2: split bf16 transposed.
#define BM 256
#define BN 128
#define BK 64
#define NTHR 512

#define OFF_AH 0u
#define OFF_AL 32768u
#define OFF_BH 65536u
#define OFF_BL 81920u
#define STG    98304u
#define GEMM_SMEM (2 * 98304)

template <int MODE>
__global__ void __launch_bounds__(NTHR, 1) gemm_sp(
    const __nv_bfloat16* __restrict__ Ah, const __nv_bfloat16* __restrict__ Al,
    const __nv_bfloat16* __restrict__ Bh, const __nv_bfloat16* __restrict__ Bl,
    float* __restrict__ Cf, __nv_bfloat16* __restrict__ Ch,
    __nv_bfloat16* __restrict__ Cl, int K, int ldc, float alpha)
{
    extern __shared__ char smem_raw[];
    const uint32_t SBASE = smem_u32(smem_raw);

    const int t    = threadIdx.x;
    const int w    = t >> 5;
    const int lane = t & 31;
    const int m0   = blockIdx.y * BM;
    const int n0   = blockIdx.x * BN;
    const int warp_m = (w >> 2) * 64;   // 0..192
    const int warp_n = (w & 3) * 32;    // 0..96

    float acc[4][4][4];
#pragma unroll
    for (int i = 0; i < 4; i++)
#pragma unroll
        for (int j = 0; j < 4; j++)
#pragma unroll
            for (int q = 0; q < 4; q++) acc[i][j][q] = 0.0f;

    // ---- cp.async plan: 12 x 16B chunks per thread per stage ----
    const int  trow = t >> 3;            // 0..63 row-within-64 group
    const int  tc8  = t & 7;             // 0..7 16B column
    const uint32_t swc = (uint32_t)tc8 * 16;
    const __nv_bfloat16* pAh = Ah + (size_t)m0 * K;
    const __nv_bfloat16* pAl = Al + (size_t)m0 * K;
    const __nv_bfloat16* pBh = Bh + (size_t)n0 * K;
    const __nv_bfloat16* pBl = Bl + (size_t)n0 * K;

    auto load_stage = [&](int s, int k0) {
        const uint32_t sb = SBASE + (uint32_t)s * STG;
#pragma unroll
        for (int i = 0; i < 12; i++) {
            int tile, row0;
            if (i < 4)       { tile = 0; row0 = i * 64; }
            else if (i < 8)  { tile = 1; row0 = (i - 4) * 64; }
            else if (i < 10) { tile = 2; row0 = (i - 8) * 64; }
            else             { tile = 3; row0 = (i - 10) * 64; }
            const __nv_bfloat16* base =
                (tile == 0) ? pAh : (tile == 1) ? pAl : (tile == 2) ? pBh : pBl;
            const uint32_t toff =
                (tile == 0) ? OFF_AH : (tile == 1) ? OFF_AL :
                (tile == 2) ? OFF_BH : OFF_BL;
            int rl = row0 + trow;
            const __nv_bfloat16* src = base + (size_t)rl * K + tc8 * 8 + k0;
            uint32_t off = toff + (uint32_t)rl * 128 +
                           (swc ^ (((uint32_t)rl & 7) << 4));
            cp16(sb + off, src);
        }
    };

    // ---- ldmatrix address precompute ----
    uint32_t a_off[4], a_xor[4];
#pragma unroll
    for (int mf = 0; mf < 4; mf++) {
        int rl = warp_m + mf * 16 + (lane & 15);
        a_off[mf] = (uint32_t)rl * 128;
        a_xor[mf] = ((uint32_t)rl & 7) << 4;
    }
    const uint32_t a_bc = ((uint32_t)lane >> 4) * 16;
    uint32_t b_off[2], b_xor[2];
#pragma unroll
    for (int nfp = 0; nfp < 2; nfp++) {
        int rl = warp_n + nfp * 16 + (lane & 7) + ((lane & 16) ? 8 : 0);
        b_off[nfp] = (uint32_t)rl * 128;
        b_xor[nfp] = ((uint32_t)rl & 7) << 4;
    }
    const uint32_t b_bc = (((uint32_t)lane >> 3) & 1) * 16;

    const int kt = K / BK;

    load_stage(0, 0);
    cp_commit();

    for (int it = 0; it < kt; it++) {
        if (it + 1 < kt) load_stage((it + 1) & 1, (it + 1) * BK);
        cp_commit();
        cp_wait1();
        __syncthreads();

        const uint32_t sb = SBASE + (uint32_t)(it & 1) * STG;

#pragma unroll
        for (int ks = 0; ks < 4; ks++) {
            const uint32_t bcA = (uint32_t)ks * 32 + a_bc;
            const uint32_t bcB = (uint32_t)ks * 32 + b_bc;
            uint32_t bh[4][2], bl[4][2];
#pragma unroll
            for (int nfp = 0; nfp < 2; nfp++) {
                uint32_t r0, r1, r2, r3;
                ldsm4(r0, r1, r2, r3, sb + OFF_BH + b_off[nfp] + (bcB ^ b_xor[nfp]));
                bh[2 * nfp][0] = r0; bh[2 * nfp][1] = r1;
                bh[2 * nfp + 1][0] = r2; bh[2 * nfp + 1][1] = r3;
                ldsm4(r0, r1, r2, r3, sb + OFF_BL + b_off[nfp] + (bcB ^ b_xor[nfp]));
                bl[2 * nfp][0] = r0; bl[2 * nfp][1] = r1;
                bl[2 * nfp + 1][0] = r2; bl[2 * nfp + 1][1] = r3;
            }
#pragma unroll
            for (int mf = 0; mf < 4; mf++) {
                uint32_t ah[4];
                ldsm4(ah[0], ah[1], ah[2], ah[3],
                      sb + OFF_AH + a_off[mf] + (bcA ^ a_xor[mf]));
#pragma unroll
                for (int nf = 0; nf < 4; nf++) {
                    mma16816(acc[mf][nf], ah, bh[nf]);
                    mma16816(acc[mf][nf], ah, bl[nf]);
                }
                uint32_t al[4];
                ldsm4(al[0], al[1], al[2], al[3],
                      sb + OFF_AL + a_off[mf] + (bcA ^ a_xor[mf]));
#pragma unroll
                for (int nf = 0; nf < 4; nf++)
                    mma16816(acc[mf][nf], al, bh[nf]);
            }
        }
        __syncthreads();
    }

    // ---- epilogue ----
#pragma unroll
    for (int mf = 0; mf < 4; mf++) {
#pragma unroll
        for (int nf = 0; nf < 4; nf++) {
            int row = m0 + warp_m + mf * 16 + (lane >> 2);
            int col = n0 + warp_n + nf * 8 + (lane & 3) * 2;
            float f00 = acc[mf][nf][0] * alpha;
            float f01 = acc[mf][nf][1] * alpha;
            float f10 = acc[mf][nf][2] * alpha;
            float f11 = acc[mf][nf][3] * alpha;
            if (MODE == 0) {
                *(float2*)(Cf + (size_t)row * ldc + col)       = make_float2(f00, f01);
                *(float2*)(Cf + (size_t)(row + 8) * ldc + col) = make_float2(f10, f11);
            } else if (MODE == 1) {
                __nv_bfloat16 h00 = __float2bfloat16(f00);
                __nv_bfloat16 h01 = __float2bfloat16(f01);
                __nv_bfloat16 h10 = __float2bfloat16(f10);
                __nv_bfloat16 h11 = __float2bfloat16(f11);
                __nv_bfloat16 l00 = __float2bfloat16(f00 - __bfloat162float(h00));
                __nv_bfloat16 l01 = __float2bfloat16(f01 - __bfloat162float(h01));
                __nv_bfloat16 l10 = __float2bfloat16(f10 - __bfloat162float(h10));
                __nv_bfloat16 l11 = __float2bfloat16(f11 - __bfloat162float(h11));
                *(__nv_bfloat162*)(Ch + (size_t)row * ldc + col)       = __halves2bfloat162(h00, h01);
                *(__nv_bfloat162*)(Ch + (size_t)(row + 8) * ldc + col) = __halves2bfloat162(h10, h11);
                *(__nv_bfloat162*)(Cl + (size_t)row * ldc + col)       = __halves2bfloat162(l00, l01);
                *(__nv_bfloat162*)(Cl + (size_t)(row + 8) * ldc + col) = __halves2bfloat162(l10, l11);
            } else { // MODE 2: transposed split: C*[col][row], ldc = M_total
                __nv_bfloat16 h00 = __float2bfloat16(f00);
                __nv_bfloat16 h01 = __float2bfloat16(f01);
                __nv_bfloat16 h10 = __float2bfloat16(f10);
                __nv_bfloat16 h11 = __float2bfloat16(f11);
                Ch[(size_t)col * ldc + row]           = h00;
                Ch[(size_t)(col + 1) * ldc + row]     = h01;
                Ch[(size_t)col * ldc + row + 8]       = h10;
                Ch[(size_t)(col + 1) * ldc + row + 8] = h11;
                Cl[(size_t)col * ldc + row]           = __float2bfloat16(f00 - __bfloat162float(h00));
                Cl[(size_t)(col + 1) * ldc + row]     = __float2bfloat16(f01 - __bfloat162float(h01));
                Cl[(size_t)col * ldc + row + 8]       = __float2bfloat16(f10 - __bfloat162float(h10));
                Cl[(size_t)(col + 1) * ldc + row + 8] = __float2bfloat16(f11 - __bfloat162float(h11));
            }
        }
    }
}

// ---------------- fp32 -> (hi,lo) bf16 split --------------------------------
__global__ void __launch_bounds__(256) split_kernel(
    const float* __restrict__ in, __nv_bfloat16* __restrict__ hi,
    __nv_bfloat16* __restrict__ lo, int n4)
{
    int i = blockIdx.x * 256 + threadIdx.x;
    if (i >= n4) return;
    float4 v = ((const float4*)in)[i];
    __nv_bfloat16 h0 = __float2bfloat16(v.x), h1 = __float2bfloat16(v.y);
    __nv_bfloat16 h2 = __float2bfloat16(v.z), h3 = __float2bfloat16(v.w);
    __nv_bfloat16 l0 = __float2bfloat16(v.x - __bfloat162float(h0));
    __nv_bfloat16 l1 = __float2bfloat16(v.y - __bfloat162float(h1));
    __nv_bfloat16 l2 = __float2bfloat16(v.z - __bfloat162float(h2));
    __nv_bfloat16 l3 = __float2bfloat16(v.w - __bfloat162float(h3));
    ((__nv_bfloat162*)hi)[2 * i]     = __halves2bfloat162(h0, h1);
    ((__nv_bfloat162*)hi)[2 * i + 1] = __halves2bfloat162(h2, h3);
    ((__nv_bfloat162*)lo)[2 * i]     = __halves2bfloat162(l0, l1);
    ((__nv_bfloat162*)lo)[2 * i + 1] = __halves2bfloat162(l2, l3);
}

// ---------------- row softmax -> split bf16 P -------------------------------
__global__ void __launch_bounds__(256) softmax_split_kernel(
    const float* __restrict__ S, __nv_bfloat16* __restrict__ Ph,
    __nv_bfloat16* __restrict__ Pl)
{
    __shared__ float red[8];
    const int row = blockIdx.x;
    const int t   = threadIdx.x;
    const float* p = S + (size_t)row * SEQ;

    float4 v[4];
#pragma unroll
    for (int i = 0; i < 4; i++)
        v[i] = *(const float4*)(p + 4 * (t + 256 * i));

    float mx = -INFINITY;
#pragma unroll
    for (int i = 0; i < 4; i++)
        mx = fmaxf(mx, fmaxf(fmaxf(v[i].x, v[i].y), fmaxf(v[i].z, v[i].w)));
#pragma unroll
    for (int o = 16; o > 0; o >>= 1)
        mx = fmaxf(mx, __shfl_xor_sync(0xFFFFFFFFu, mx, o));
    if ((t & 31) == 0) red[t >> 5] = mx;
    __syncthreads();
    {
        float m = red[t & 7];
#pragma unroll
        for (int o = 4; o > 0; o >>= 1)
            m = fmaxf(m, __shfl_xor_sync(0xFFFFFFFFu, m, o));
        mx = m;
    }
    __syncthreads();

    float sum = 0.0f;
#pragma unroll
    for (int i = 0; i < 4; i++) {
        v[i].x = expf(v[i].x - mx); v[i].y = expf(v[i].y - mx);
        v[i].z = expf(v[i].z - mx); v[i].w = expf(v[i].w - mx);
        sum += v[i].x + v[i].y + v[i].z + v[i].w;
    }
#pragma unroll
    for (int o = 16; o > 0; o >>= 1)
        sum += __shfl_xor_sync(0xFFFFFFFFu, sum, o);
    if ((t & 31) == 0) red[t >> 5] = sum;
    __syncthreads();
    {
        float s2 = red[t & 7];
#pragma unroll
        for (int o = 4; o > 0; o >>= 1)
            s2 += __shfl_xor_sync(0xFFFFFFFFu, s2, o);
        sum = s2;
    }

    const float inv = 1.0f / sum;
#pragma unroll
    for (int i = 0; i < 4; i++) {
        size_t idx = (size_t)row * SEQ + 4 * (t + 256 * i);
        float f0 = v[i].x * inv, f1 = v[i].y * inv;
        float f2 = v[i].z * inv, f3 = v[i].w * inv;
        __nv_bfloat16 h0 = __float2bfloat16(f0), h1 = __float2bfloat16(f1);
        __nv_bfloat16 h2 = __float2bfloat16(f2), h3 = __float2bfloat16(f3);
        __nv_bfloat16 l0 = __float2bfloat16(f0 - __bfloat162float(h0));
        __nv_bfloat16 l1 = __float2bfloat16(f1 - __bfloat162float(h1));
        __nv_bfloat16 l2 = __float2bfloat16(f2 - __bfloat162float(h2));
        __nv_bfloat16 l3 = __float2bfloat16(f3 - __bfloat162float(h3));
        *(__nv_bfloat162*)(Ph + idx)     = __halves2bfloat162(h0, h1);
        *(__nv_bfloat162*)(Ph + idx + 2) = __halves2bfloat162(h2, h3);
        *(__nv_bfloat162*)(Pl + idx)     = __halves2bfloat162(l0, l1);
        *(__nv_bfloat162*)(Pl + idx + 2) = __halves2bfloat162(l2, l3);
    }
}

// ---------------------------------------------------------------------------
extern "C" void kernel_launch(void* const* d_in, const int* in_sizes, int n_in,
                              void* d_out, int out_size)
{
    (void)in_sizes; (void)n_in; (void)out_size;
    const float* X  = (const float*)d_in[0];
    const float* WQ = (const float*)d_in[1];
    const float* WK = (const float*)d_in[2];
    const float* WV = (const float*)d_in[3];
    float* O = (float*)d_out;

    __nv_bfloat16 *Xh, *Xl, *WQh, *WQl, *WKh, *WKl, *WVh, *WVl;
    __nv_bfloat16 *Qh, *Ql, *Kh, *Kl, *Vth, *Vtl, *Ph, *Pl;
    float* S;
    cudaGetSymbolAddress((void**)&Xh, g_Xh);   cudaGetSymbolAddress((void**)&Xl, g_Xl);
    cudaGetSymbolAddress((void**)&WQh, g_WQh); cudaGetSymbolAddress((void**)&WQl, g_WQl);
    cudaGetSymbolAddress((void**)&WKh, g_WKh); cudaGetSymbolAddress((void**)&WKl, g_WKl);
    cudaGetSymbolAddress((void**)&WVh, g_WVh); cudaGetSymbolAddress((void**)&WVl, g_WVl);
    cudaGetSymbolAddress((void**)&Qh, g_Qh);   cudaGetSymbolAddress((void**)&Ql, g_Ql);
    cudaGetSymbolAddress((void**)&Kh, g_Kh);   cudaGetSymbolAddress((void**)&Kl, g_Kl);
    cudaGetSymbolAddress((void**)&Vth, g_Vth); cudaGetSymbolAddress((void**)&Vtl, g_Vtl);
    cudaGetSymbolAddress((void**)&Ph, g_Ph);   cudaGetSymbolAddress((void**)&Pl, g_Pl);
    cudaGetSymbolAddress((void**)&S, g_S);

    cudaFuncSetAttribute(gemm_sp<0>, cudaFuncAttributeMaxDynamicSharedMemorySize, GEMM_SMEM);
    cudaFuncSetAttribute(gemm_sp<1>, cudaFuncAttributeMaxDynamicSharedMemorySize, GEMM_SMEM);
    cudaFuncSetAttribute(gemm_sp<2>, cudaFuncAttributeMaxDynamicSharedMemorySize, GEMM_SMEM);

    // 1) split inputs to (hi, lo) bf16
    {
        int n4 = SEQ * EMB / 4;
        split_kernel<<<(n4 + 255) / 256, 256>>>(X, Xh, Xl, n4);
        int w4 = OUTD * EMB / 4;
        split_kernel<<<(w4 + 255) / 256, 256>>>(WQ, WQh, WQl, w4);
        split_kernel<<<(w4 + 255) / 256, 256>>>(WK, WKh, WKl, w4);
        split_kernel<<<(w4 + 255) / 256, 256>>>(WV, WVh, WVl, w4);
    }

    dim3 thr(NTHR);

    // 2) projections (NT, 3-term): Q,K split-bf16; V split + transposed
    dim3 gp(OUTD / BN, SEQ / BM);
    gemm_sp<1><<<gp, thr, GEMM_SMEM>>>(Xh, Xl, WQh, WQl, nullptr, Qh, Ql, EMB, OUTD, 1.0f);
    gemm_sp<1><<<gp, thr, GEMM_SMEM>>>(Xh, Xl, WKh, WKl, nullptr, Kh, Kl, EMB, OUTD, 1.0f);
    gemm_sp<2><<<gp, thr, GEMM_SMEM>>>(Xh, Xl, WVh, WVl, nullptr, Vth, Vtl, EMB, SEQ, 1.0f);

    // 3) scores (3-term): S = (Q @ K^T) / 32
    dim3 gs(SEQ / BN, SEQ / BM);
    gemm_sp<0><<<gs, thr, GEMM_SMEM>>>(Qh, Ql, Kh, Kl, S, nullptr, nullptr, OUTD, SEQ, 0.03125f);

    // 4) softmax -> split bf16 P
    softmax_split_kernel<<<SEQ, 256>>>(S, Ph, Pl);

    // 5) O = P @ V (3-term), B = V^T
    dim3 go(OUTD / BN, SEQ / BM);
    gemm_sp<0><<<go, thr, GEMM_SMEM>>>(Ph, Pl, Vth, Vtl, O, nullptr, nullptr, SEQ, OUTD, 1.0f);
}

// round 8
// speedup vs baseline: 4.0869x; 1.3854x over previous
#include <cuda_runtime.h>
#include <cuda_fp16.h>
#include <stdint.h>
#include <stddef.h>
#include <math.h>

#define SEQ 4096
#define EMB 1024
#define OUTD 1024

// ---------------- scratch (__device__ globals; allocation-free rule) -------
__device__ __half g_Xh[(size_t)SEQ * EMB];
__device__ __half g_WQh[(size_t)OUTD * EMB], g_WQl[(size_t)OUTD * EMB];
__device__ __half g_WKh[(size_t)OUTD * EMB], g_WKl[(size_t)OUTD * EMB];
__device__ __half g_WVh[(size_t)OUTD * EMB], g_WVl[(size_t)OUTD * EMB];
__device__ __half g_Qh[(size_t)SEQ * OUTD];
__device__ __half g_Kh[(size_t)SEQ * OUTD], g_Kl[(size_t)SEQ * OUTD];
__device__ __half g_Vth[(size_t)OUTD * SEQ], g_Vtl[(size_t)OUTD * SEQ];   // V^T
__device__ float  g_S[(size_t)SEQ * SEQ];
__device__ __half g_Ph[(size_t)SEQ * SEQ];

// ---------------- PTX helpers ----------------------------------------------
__device__ __forceinline__ uint32_t smem_u32(const void* p) {
    uint32_t a;
    asm("{ .reg .u64 t; cvta.to.shared.u64 t, %1; cvt.u32.u64 %0, t; }"
        : "=r"(a) : "l"(p));
    return a;
}
__device__ __forceinline__ void cp16(uint32_t dst, const void* src) {
    asm volatile("cp.async.cg.shared.global [%0], [%1], 16;" :: "r"(dst), "l"(src));
}
__device__ __forceinline__ void cp_commit() {
    asm volatile("cp.async.commit_group;" ::: "memory");
}
__device__ __forceinline__ void cp_wait2() {
    asm volatile("cp.async.wait_group 2;" ::: "memory");
}
__device__ __forceinline__ void ldsm4(uint32_t& r0, uint32_t& r1, uint32_t& r2,
                                      uint32_t& r3, uint32_t addr) {
    asm volatile("ldmatrix.sync.aligned.m8n8.x4.shared.b16 {%0,%1,%2,%3}, [%4];"
                 : "=r"(r0), "=r"(r1), "=r"(r2), "=r"(r3) : "r"(addr));
}
__device__ __forceinline__ void mma16816(float* c, const uint32_t* a,
                                         const uint32_t* b) {
    asm volatile(
        "mma.sync.aligned.m16n8k16.row.col.f32.f16.f16.f32 "
        "{%0,%1,%2,%3}, {%4,%5,%6,%7}, {%8,%9}, {%0,%1,%2,%3};"
        : "+f"(c[0]), "+f"(c[1]), "+f"(c[2]), "+f"(c[3])
        : "r"(a[0]), "r"(a[1]), "r"(a[2]), "r"(a[3]), "r"(b[0]), "r"(b[1]));
}

// ---------------- 2-term fp16 warp-MMA GEMM --------------------------------
// C[M,N] = alpha * A[M,K] @ (Bh+Bl)[N,K]^T, K-major rows.
// A single fp16; B fp16 (hi,lo) pair. Terms: A*Bh + A*Bl.
// CTA 256x128, BK=64, 3 cp.async stages, 16 warps (4M x 4N), warp tile 64x32.
// MODE 0: fp32 C. MODE 1: fp16 single C1. MODE 2: fp16 pair C1/C2.
// MODE 3: fp16 pair transposed (C*[col][row], ldc = M_total).
#define BM 256
#define BN 128
#define BK 64
#define NTHR 512

#define OFF_A  0u
#define OFF_BH 32768u
#define OFF_BL 49152u
#define STG    65536u
#define GEMM_SMEM (3 * 65536)

template <int MODE>
__global__ void __launch_bounds__(NTHR, 1) gemm_2t(
    const __half* __restrict__ A, const __half* __restrict__ Bh,
    const __half* __restrict__ Bl, float* __restrict__ Cf,
    __half* __restrict__ C1, __half* __restrict__ C2,
    int K, int ldc, float alpha)
{
    extern __shared__ char smem_raw[];
    const uint32_t SBASE = smem_u32(smem_raw);

    const int t    = threadIdx.x;
    const int w    = t >> 5;
    const int lane = t & 31;
    const int m0   = blockIdx.y * BM;
    const int n0   = blockIdx.x * BN;
    const int warp_m = (w >> 2) * 64;   // 0..192
    const int warp_n = (w & 3) * 32;    // 0..96

    float acc[4][4][4];
#pragma unroll
    for (int i = 0; i < 4; i++)
#pragma unroll
        for (int j = 0; j < 4; j++)
#pragma unroll
            for (int q = 0; q < 4; q++) acc[i][j][q] = 0.0f;

    // ---- cp.async plan: 8 x 16B chunks per thread per stage ----
    const int trow = t >> 3;             // 0..63
    const int tc8  = t & 7;              // 0..7
    const uint32_t swc = (uint32_t)tc8 * 16;
    const __half* pA  = A  + (size_t)m0 * K;
    const __half* pBh = Bh + (size_t)n0 * K;
    const __half* pBl = Bl + (size_t)n0 * K;

    auto load_stage = [&](int s, int k0) {
        const uint32_t sb = SBASE + (uint32_t)s * STG;
#pragma unroll
        for (int i = 0; i < 8; i++) {
            int tile, row0;
            if (i < 4)      { tile = 0; row0 = i * 64; }
            else if (i < 6) { tile = 1; row0 = (i - 4) * 64; }
            else            { tile = 2; row0 = (i - 6) * 64; }
            const __half* base = (tile == 0) ? pA : (tile == 1) ? pBh : pBl;
            const uint32_t toff =
                (tile == 0) ? OFF_A : (tile == 1) ? OFF_BH : OFF_BL;
            int rl = row0 + trow;
            const __half* src = base + (size_t)rl * K + tc8 * 8 + k0;
            uint32_t off = toff + (uint32_t)rl * 128 +
                           (swc ^ (((uint32_t)rl & 7) << 4));
            cp16(sb + off, src);
        }
    };

    // ---- ldmatrix address precompute ----
    uint32_t a_off[4], a_xor[4];
#pragma unroll
    for (int mf = 0; mf < 4; mf++) {
        int rl = warp_m + mf * 16 + (lane & 15);
        a_off[mf] = (uint32_t)rl * 128;
        a_xor[mf] = ((uint32_t)rl & 7) << 4;
    }
    const uint32_t a_bc = ((uint32_t)lane >> 4) * 16;
    uint32_t b_off[2], b_xor[2];
#pragma unroll
    for (int nfp = 0; nfp < 2; nfp++) {
        int rl = warp_n + nfp * 16 + (lane & 7) + ((lane & 16) ? 8 : 0);
        b_off[nfp] = (uint32_t)rl * 128;
        b_xor[nfp] = ((uint32_t)rl & 7) << 4;
    }
    const uint32_t b_bc = (((uint32_t)lane >> 3) & 1) * 16;

    const int kt = K / BK;

    // prologue: stages 0,1
    load_stage(0, 0);      cp_commit();
    load_stage(1, BK);     cp_commit();

    for (int it = 0; it < kt; it++) {
        if (it + 2 < kt) load_stage((it + 2) % 3, (it + 2) * BK);
        cp_commit();                       // always (possibly empty group)
        cp_wait2();                        // stage `it` is now resident
        __syncthreads();

        const uint32_t sb = SBASE + (uint32_t)(it % 3) * STG;

#pragma unroll
        for (int ks = 0; ks < 4; ks++) {
            const uint32_t bcA = (uint32_t)ks * 32 + a_bc;
            const uint32_t bcB = (uint32_t)ks * 32 + b_bc;
            uint32_t bh[4][2], bl[4][2];
#pragma unroll
            for (int nfp = 0; nfp < 2; nfp++) {
                uint32_t r0, r1, r2, r3;
                ldsm4(r0, r1, r2, r3, sb + OFF_BH + b_off[nfp] + (bcB ^ b_xor[nfp]));
                bh[2 * nfp][0] = r0; bh[2 * nfp][1] = r1;
                bh[2 * nfp + 1][0] = r2; bh[2 * nfp + 1][1] = r3;
                ldsm4(r0, r1, r2, r3, sb + OFF_BL + b_off[nfp] + (bcB ^ b_xor[nfp]));
                bl[2 * nfp][0] = r0; bl[2 * nfp][1] = r1;
                bl[2 * nfp + 1][0] = r2; bl[2 * nfp + 1][1] = r3;
            }
#pragma unroll
            for (int mf = 0; mf < 4; mf++) {
                uint32_t ah[4];
                ldsm4(ah[0], ah[1], ah[2], ah[3],
                      sb + OFF_A + a_off[mf] + (bcA ^ a_xor[mf]));
#pragma unroll
                for (int nf = 0; nf < 4; nf++) {
                    mma16816(acc[mf][nf], ah, bh[nf]);
                    mma16816(acc[mf][nf], ah, bl[nf]);
                }
            }
        }
        __syncthreads();
    }

    // ---- epilogue ----
#pragma unroll
    for (int mf = 0; mf < 4; mf++) {
#pragma unroll
        for (int nf = 0; nf < 4; nf++) {
            int row = m0 + warp_m + mf * 16 + (lane >> 2);
            int col = n0 + warp_n + nf * 8 + (lane & 3) * 2;
            float f00 = acc[mf][nf][0] * alpha;
            float f01 = acc[mf][nf][1] * alpha;
            float f10 = acc[mf][nf][2] * alpha;
            float f11 = acc[mf][nf][3] * alpha;
            if (MODE == 0) {
                *(float2*)(Cf + (size_t)row * ldc + col)       = make_float2(f00, f01);
                *(float2*)(Cf + (size_t)(row + 8) * ldc + col) = make_float2(f10, f11);
            } else if (MODE == 1) {
                *(__half2*)(C1 + (size_t)row * ldc + col) =
                    __halves2half2(__float2half_rn(f00), __float2half_rn(f01));
                *(__half2*)(C1 + (size_t)(row + 8) * ldc + col) =
                    __halves2half2(__float2half_rn(f10), __float2half_rn(f11));
            } else if (MODE == 2) {
                __half h00 = __float2half_rn(f00), h01 = __float2half_rn(f01);
                __half h10 = __float2half_rn(f10), h11 = __float2half_rn(f11);
                __half l00 = __float2half_rn(f00 - __half2float(h00));
                __half l01 = __float2half_rn(f01 - __half2float(h01));
                __half l10 = __float2half_rn(f10 - __half2float(h10));
                __half l11 = __float2half_rn(f11 - __half2float(h11));
                *(__half2*)(C1 + (size_t)row * ldc + col)       = __halves2half2(h00, h01);
                *(__half2*)(C1 + (size_t)(row + 8) * ldc + col) = __halves2half2(h10, h11);
                *(__half2*)(C2 + (size_t)row * ldc + col)       = __halves2half2(l00, l01);
                *(__half2*)(C2 + (size_t)(row + 8) * ldc + col) = __halves2half2(l10, l11);
            } else { // MODE 3: transposed pair: C*[col][row], ldc = M_total
                __half h00 = __float2half_rn(f00), h01 = __float2half_rn(f01);
                __half h10 = __float2half_rn(f10), h11 = __float2half_rn(f11);
                C1[(size_t)col * ldc + row]           = h00;
                C1[(size_t)(col + 1) * ldc + row]     = h01;
                C1[(size_t)col * ldc + row + 8]       = h10;
                C1[(size_t)(col + 1) * ldc + row + 8] = h11;
                C2[(size_t)col * ldc + row]           = __float2half_rn(f00 - __half2float(h00));
                C2[(size_t)(col + 1) * ldc + row]     = __float2half_rn(f01 - __half2float(h01));
                C2[(size_t)col * ldc + row + 8]       = __float2half_rn(f10 - __half2float(h10));
                C2[(size_t)(col + 1) * ldc + row + 8] = __float2half_rn(f11 - __half2float(h11));
            }
        }
    }
}

// ---------------- fp32 -> fp16 single convert -------------------------------
__global__ void __launch_bounds__(256) conv_half_kernel(
    const float* __restrict__ in, __half* __restrict__ out, int n4)
{
    int i = blockIdx.x * 256 + threadIdx.x;
    if (i >= n4) return;
    float4 v = ((const float4*)in)[i];
    ((__half2*)out)[2 * i]     = __halves2half2(__float2half_rn(v.x), __float2half_rn(v.y));
    ((__half2*)out)[2 * i + 1] = __halves2half2(__float2half_rn(v.z), __float2half_rn(v.w));
}

// ---------------- fp32 -> (hi,lo) fp16 pair split ---------------------------
__global__ void __launch_bounds__(256) split_pair_kernel(
    const float* __restrict__ in, __half* __restrict__ hi,
    __half* __restrict__ lo, int n4)
{
    int i = blockIdx.x * 256 + threadIdx.x;
    if (i >= n4) return;
    float4 v = ((const float4*)in)[i];
    __half h0 = __float2half_rn(v.x), h1 = __float2half_rn(v.y);
    __half h2 = __float2half_rn(v.z), h3 = __float2half_rn(v.w);
    __half l0 = __float2half_rn(v.x - __half2float(h0));
    __half l1 = __float2half_rn(v.y - __half2float(h1));
    __half l2 = __float2half_rn(v.z - __half2float(h2));
    __half l3 = __float2half_rn(v.w - __half2float(h3));
    ((__half2*)hi)[2 * i]     = __halves2half2(h0, h1);
    ((__half2*)hi)[2 * i + 1] = __halves2half2(h2, h3);
    ((__half2*)lo)[2 * i]     = __halves2half2(l0, l1);
    ((__half2*)lo)[2 * i + 1] = __halves2half2(l2, l3);
}

// ---------------- row softmax -> fp16 Ph ------------------------------------
__global__ void __launch_bounds__(256) softmax_h_kernel(
    const float* __restrict__ S, __half* __restrict__ Ph)
{
    __shared__ float red[8];
    const int row = blockIdx.x;
    const int t   = threadIdx.x;
    const float* p = S + (size_t)row * SEQ;

    float4 v[4];
#pragma unroll
    for (int i = 0; i < 4; i++)
        v[i] = *(const float4*)(p + 4 * (t + 256 * i));

    float mx = -INFINITY;
#pragma unroll
    for (int i = 0; i < 4; i++)
        mx = fmaxf(mx, fmaxf(fmaxf(v[i].x, v[i].y), fmaxf(v[i].z, v[i].w)));
#pragma unroll
    for (int o = 16; o > 0; o >>= 1)
        mx = fmaxf(mx, __shfl_xor_sync(0xFFFFFFFFu, mx, o));
    if ((t & 31) == 0) red[t >> 5] = mx;
    __syncthreads();
    {
        float m = red[t & 7];
#pragma unroll
        for (int o = 4; o > 0; o >>= 1)
            m = fmaxf(m, __shfl_xor_sync(0xFFFFFFFFu, m, o));
        mx = m;
    }
    __syncthreads();

    float sum = 0.0f;
#pragma unroll
    for (int i = 0; i < 4; i++) {
        v[i].x = expf(v[i].x - mx); v[i].y = expf(v[i].y - mx);
        v[i].z = expf(v[i].z - mx); v[i].w = expf(v[i].w - mx);
        sum += v[i].x + v[i].y + v[i].z + v[i].w;
    }
#pragma unroll
    for (int o = 16; o > 0; o >>= 1)
        sum += __shfl_xor_sync(0xFFFFFFFFu, sum, o);
    if ((t & 31) == 0) red[t >> 5] = sum;
    __syncthreads();
    {
        float s2 = red[t & 7];
#pragma unroll
        for (int o = 4; o > 0; o >>= 1)
            s2 += __shfl_xor_sync(0xFFFFFFFFu, s2, o);
        sum = s2;
    }

    const float inv = 1.0f / sum;
#pragma unroll
    for (int i = 0; i < 4; i++) {
        size_t idx = (size_t)row * SEQ + 4 * (t + 256 * i);
        *(__half2*)(Ph + idx) = __halves2half2(
            __float2half_rn(v[i].x * inv), __float2half_rn(v[i].y * inv));
        *(__half2*)(Ph + idx + 2) = __halves2half2(
            __float2half_rn(v[i].z * inv), __float2half_rn(v[i].w * inv));
    }
}

// ---------------------------------------------------------------------------
extern "C" void kernel_launch(void* const* d_in, const int* in_sizes, int n_in,
                              void* d_out, int out_size)
{
    (void)in_sizes; (void)n_in; (void)out_size;
    const float* X  = (const float*)d_in[0];
    const float* WQ = (const float*)d_in[1];
    const float* WK = (const float*)d_in[2];
    const float* WV = (const float*)d_in[3];
    float* O = (float*)d_out;

    __half *Xh, *WQh, *WQl, *WKh, *WKl, *WVh, *WVl;
    __half *Qh, *Kh, *Kl, *Vth, *Vtl, *Ph;
    float* S;
    cudaGetSymbolAddress((void**)&Xh, g_Xh);
    cudaGetSymbolAddress((void**)&WQh, g_WQh); cudaGetSymbolAddress((void**)&WQl, g_WQl);
    cudaGetSymbolAddress((void**)&WKh, g_WKh); cudaGetSymbolAddress((void**)&WKl, g_WKl);
    cudaGetSymbolAddress((void**)&WVh, g_WVh); cudaGetSymbolAddress((void**)&WVl, g_WVl);
    cudaGetSymbolAddress((void**)&Qh, g_Qh);
    cudaGetSymbolAddress((void**)&Kh, g_Kh);   cudaGetSymbolAddress((void**)&Kl, g_Kl);
    cudaGetSymbolAddress((void**)&Vth, g_Vth); cudaGetSymbolAddress((void**)&Vtl, g_Vtl);
    cudaGetSymbolAddress((void**)&Ph, g_Ph);
    cudaGetSymbolAddress((void**)&S, g_S);

    cudaFuncSetAttribute(gemm_2t<0>, cudaFuncAttributeMaxDynamicSharedMemorySize, GEMM_SMEM);
    cudaFuncSetAttribute(gemm_2t<1>, cudaFuncAttributeMaxDynamicSharedMemorySize, GEMM_SMEM);
    cudaFuncSetAttribute(gemm_2t<2>, cudaFuncAttributeMaxDynamicSharedMemorySize, GEMM_SMEM);
    cudaFuncSetAttribute(gemm_2t<3>, cudaFuncAttributeMaxDynamicSharedMemorySize, GEMM_SMEM);

    // 1) input conversions
    {
        int n4 = SEQ * EMB / 4;
        conv_half_kernel<<<(n4 + 255) / 256, 256>>>(X, Xh, n4);
        int w4 = OUTD * EMB / 4;
        split_pair_kernel<<<(w4 + 255) / 256, 256>>>(WQ, WQh, WQl, w4);
        split_pair_kernel<<<(w4 + 255) / 256, 256>>>(WK, WKh, WKl, w4);
        split_pair_kernel<<<(w4 + 255) / 256, 256>>>(WV, WVh, WVl, w4);
    }

    dim3 thr(NTHR);

    // 2) projections: Q single fp16; K pair; V pair transposed
    dim3 gp(OUTD / BN, SEQ / BM);
    gemm_2t<1><<<gp, thr, GEMM_SMEM>>>(Xh, WQh, WQl, nullptr, Qh, nullptr, EMB, OUTD, 1.0f);
    gemm_2t<2><<<gp, thr, GEMM_SMEM>>>(Xh, WKh, WKl, nullptr, Kh, Kl, EMB, OUTD, 1.0f);
    gemm_2t<3><<<gp, thr, GEMM_SMEM>>>(Xh, WVh, WVl, nullptr, Vth, Vtl, EMB, SEQ, 1.0f);

    // 3) scores: S = (Q @ K^T) / 32
    dim3 gs(SEQ / BN, SEQ / BM);
    gemm_2t<0><<<gs, thr, GEMM_SMEM>>>(Qh, Kh, Kl, S, nullptr, nullptr, OUTD, SEQ, 0.03125f);

    // 4) softmax -> fp16 Ph
    softmax_h_kernel<<<SEQ, 256>>>(S, Ph);

    // 5) O = P @ V, B = V^T pair
    dim3 go(OUTD / BN, SEQ / BM);
    gemm_2t<0><<<go, thr, GEMM_SMEM>>>(Ph, Vth, Vtl, O, nullptr, nullptr, SEQ, OUTD, 1.0f);
}

// round 9
// speedup vs baseline: 4.0960x; 1.0022x over previous
#include <cuda_runtime.h>
#include <cuda_fp16.h>
#include <stdint.h>
#include <stddef.h>
#include <math.h>

#define SEQ 4096
#define EMB 1024
#define OUTD 1024

// ---------------- scratch (__device__ globals; allocation-free rule) -------
__device__ __half g_Xh[(size_t)SEQ * EMB];
__device__ __half g_WQh[(size_t)OUTD * EMB], g_WQl[(size_t)OUTD * EMB];
__device__ __half g_WKh[(size_t)OUTD * EMB], g_WKl[(size_t)OUTD * EMB];
__device__ __half g_WVh[(size_t)OUTD * EMB], g_WVl[(size_t)OUTD * EMB];
__device__ __half g_Qh[(size_t)SEQ * OUTD];
__device__ __half g_Kh[(size_t)SEQ * OUTD], g_Kl[(size_t)SEQ * OUTD];
__device__ __half g_Vth[(size_t)OUTD * SEQ], g_Vtl[(size_t)OUTD * SEQ];   // V^T
__device__ float  g_S[(size_t)SEQ * SEQ];
__device__ __half g_Ph[(size_t)SEQ * SEQ];

// ---------------- PTX helpers ----------------------------------------------
__device__ __forceinline__ uint32_t smem_u32(const void* p) {
    uint32_t a;
    asm("{ .reg .u64 t; cvta.to.shared.u64 t, %1; cvt.u32.u64 %0, t; }"
        : "=r"(a) : "l"(p));
    return a;
}
__device__ __forceinline__ void cp16(uint32_t dst, const void* src) {
    asm volatile("cp.async.cg.shared.global [%0], [%1], 16;" :: "r"(dst), "l"(src));
}
__device__ __forceinline__ void cp_commit() {
    asm volatile("cp.async.commit_group;" ::: "memory");
}
__device__ __forceinline__ void cp_wait2() {
    asm volatile("cp.async.wait_group 2;" ::: "memory");
}
__device__ __forceinline__ void ldsm4(uint32_t& r0, uint32_t& r1, uint32_t& r2,
                                      uint32_t& r3, uint32_t addr) {
    asm volatile("ldmatrix.sync.aligned.m8n8.x4.shared.b16 {%0,%1,%2,%3}, [%4];"
                 : "=r"(r0), "=r"(r1), "=r"(r2), "=r"(r3) : "r"(addr));
}
__device__ __forceinline__ void mma16816(float* c, const uint32_t* a,
                                         const uint32_t* b) {
    asm volatile(
        "mma.sync.aligned.m16n8k16.row.col.f32.f16.f16.f32 "
        "{%0,%1,%2,%3}, {%4,%5,%6,%7}, {%8,%9}, {%0,%1,%2,%3};"
        : "+f"(c[0]), "+f"(c[1]), "+f"(c[2]), "+f"(c[3])
        : "r"(a[0]), "r"(a[1]), "r"(a[2]), "r"(a[3]), "r"(b[0]), "r"(b[1]));
}

// ---------------- 2-term fp16 warp-MMA GEMM --------------------------------
// C[M,N] = alpha * A[M,K] @ (Bh+Bl)[N,K]^T, K-major rows.
// A single fp16; B fp16 (hi,lo) pair. Terms: A*Bh + A*Bl.
// CTA 256x128, BK=64, 3 cp.async stages, 16 warps (4M x 4N), warp tile 64x32.
// MODE 0: fp32 C. MODE 1: fp16 single C1. MODE 2: fp16 pair C1/C2.
// MODE 3: fp16 pair transposed (C*[col][row], ldc = M_total).
#define BM 256
#define BN 128
#define BK 64
#define NTHR 512

#define OFF_A  0u
#define OFF_BH 32768u
#define OFF_BL 49152u
#define STG    65536u
#define GEMM_SMEM (3 * 65536)

template <int MODE>
__global__ void __launch_bounds__(NTHR, 1) gemm_2t(
    const __half* __restrict__ A, const __half* __restrict__ Bh,
    const __half* __restrict__ Bl, float* __restrict__ Cf,
    __half* __restrict__ C1, __half* __restrict__ C2,
    int K, int ldc, float alpha)
{
    extern __shared__ char smem_raw[];
    const uint32_t SBASE = smem_u32(smem_raw);

    const int t    = threadIdx.x;
    const int w    = t >> 5;
    const int lane = t & 31;
    const int m0   = blockIdx.y * BM;
    const int n0   = blockIdx.x * BN;
    const int warp_m = (w >> 2) * 64;   // 0..192
    const int warp_n = (w & 3) * 32;    // 0..96

    float acc[4][4][4];
#pragma unroll
    for (int i = 0; i < 4; i++)
#pragma unroll
        for (int j = 0; j < 4; j++)
#pragma unroll
            for (int q = 0; q < 4; q++) acc[i][j][q] = 0.0f;

    // ---- cp.async plan: 8 x 16B chunks per thread per stage ----
    const int trow = t >> 3;             // 0..63
    const int tc8  = t & 7;              // 0..7
    const uint32_t swc = (uint32_t)tc8 * 16;
    const __half* pA  = A  + (size_t)m0 * K;
    const __half* pBh = Bh + (size_t)n0 * K;
    const __half* pBl = Bl + (size_t)n0 * K;

    auto load_stage = [&](int s, int k0) {
        const uint32_t sb = SBASE + (uint32_t)s * STG;
#pragma unroll
        for (int i = 0; i < 8; i++) {
            int tile, row0;
            if (i < 4)      { tile = 0; row0 = i * 64; }
            else if (i < 6) { tile = 1; row0 = (i - 4) * 64; }
            else            { tile = 2; row0 = (i - 6) * 64; }
            const __half* base = (tile == 0) ? pA : (tile == 1) ? pBh : pBl;
            const uint32_t toff =
                (tile == 0) ? OFF_A : (tile == 1) ? OFF_BH : OFF_BL;
            int rl = row0 + trow;
            const __half* src = base + (size_t)rl * K + tc8 * 8 + k0;
            uint32_t off = toff + (uint32_t)rl * 128 +
                           (swc ^ (((uint32_t)rl & 7) << 4));
            cp16(sb + off, src);
        }
    };

    // ---- ldmatrix address precompute ----
    uint32_t a_off[4], a_xor[4];
#pragma unroll
    for (int mf = 0; mf < 4; mf++) {
        int rl = warp_m + mf * 16 + (lane & 15);
        a_off[mf] = (uint32_t)rl * 128;
        a_xor[mf] = ((uint32_t)rl & 7) << 4;
    }
    const uint32_t a_bc = ((uint32_t)lane >> 4) * 16;
    uint32_t b_off[2], b_xor[2];
#pragma unroll
    for (int nfp = 0; nfp < 2; nfp++) {
        int rl = warp_n + nfp * 16 + (lane & 7) + ((lane & 16) ? 8 : 0);
        b_off[nfp] = (uint32_t)rl * 128;
        b_xor[nfp] = ((uint32_t)rl & 7) << 4;
    }
    const uint32_t b_bc = (((uint32_t)lane >> 3) & 1) * 16;

    const int kt = K / BK;

    // prologue: stages 0,1
    load_stage(0, 0);      cp_commit();
    load_stage(1, BK);     cp_commit();

    for (int it = 0; it < kt; it++) {
        if (it + 2 < kt) load_stage((it + 2) % 3, (it + 2) * BK);
        cp_commit();                       // always (possibly empty group)
        cp_wait2();                        // stage `it` is now resident
        __syncthreads();

        const uint32_t sb = SBASE + (uint32_t)(it % 3) * STG;

#pragma unroll
        for (int ks = 0; ks < 4; ks++) {
            const uint32_t bcA = (uint32_t)ks * 32 + a_bc;
            const uint32_t bcB = (uint32_t)ks * 32 + b_bc;
            uint32_t bh[4][2], bl[4][2];
#pragma unroll
            for (int nfp = 0; nfp < 2; nfp++) {
                uint32_t r0, r1, r2, r3;
                ldsm4(r0, r1, r2, r3, sb + OFF_BH + b_off[nfp] + (bcB ^ b_xor[nfp]));
                bh[2 * nfp][0] = r0; bh[2 * nfp][1] = r1;
                bh[2 * nfp + 1][0] = r2; bh[2 * nfp + 1][1] = r3;
                ldsm4(r0, r1, r2, r3, sb + OFF_BL + b_off[nfp] + (bcB ^ b_xor[nfp]));
                bl[2 * nfp][0] = r0; bl[2 * nfp][1] = r1;
                bl[2 * nfp + 1][0] = r2; bl[2 * nfp + 1][1] = r3;
            }
#pragma unroll
            for (int mf = 0; mf < 4; mf++) {
                uint32_t ah[4];
                ldsm4(ah[0], ah[1], ah[2], ah[3],
                      sb + OFF_A + a_off[mf] + (bcA ^ a_xor[mf]));
#pragma unroll
                for (int nf = 0; nf < 4; nf++) {
                    mma16816(acc[mf][nf], ah, bh[nf]);
                    mma16816(acc[mf][nf], ah, bl[nf]);
                }
            }
        }
        __syncthreads();
    }

    // ---- epilogue ----
#pragma unroll
    for (int mf = 0; mf < 4; mf++) {
#pragma unroll
        for (int nf = 0; nf < 4; nf++) {
            int row = m0 + warp_m + mf * 16 + (lane >> 2);
            int col = n0 + warp_n + nf * 8 + (lane & 3) * 2;
            float f00 = acc[mf][nf][0] * alpha;
            float f01 = acc[mf][nf][1] * alpha;
            float f10 = acc[mf][nf][2] * alpha;
            float f11 = acc[mf][nf][3] * alpha;
            if (MODE == 0) {
                *(float2*)(Cf + (size_t)row * ldc + col)       = make_float2(f00, f01);
                *(float2*)(Cf + (size_t)(row + 8) * ldc + col) = make_float2(f10, f11);
            } else if (MODE == 1) {
                *(__half2*)(C1 + (size_t)row * ldc + col) =
                    __halves2half2(__float2half_rn(f00), __float2half_rn(f01));
                *(__half2*)(C1 + (size_t)(row + 8) * ldc + col) =
                    __halves2half2(__float2half_rn(f10), __float2half_rn(f11));
            } else if (MODE == 2) {
                __half h00 = __float2half_rn(f00), h01 = __float2half_rn(f01);
                __half h10 = __float2half_rn(f10), h11 = __float2half_rn(f11);
                __half l00 = __float2half_rn(f00 - __half2float(h00));
                __half l01 = __float2half_rn(f01 - __half2float(h01));
                __half l10 = __float2half_rn(f10 - __half2float(h10));
                __half l11 = __float2half_rn(f11 - __half2float(h11));
                *(__half2*)(C1 + (size_t)row * ldc + col)       = __halves2half2(h00, h01);
                *(__half2*)(C1 + (size_t)(row + 8) * ldc + col) = __halves2half2(h10, h11);
                *(__half2*)(C2 + (size_t)row * ldc + col)       = __halves2half2(l00, l01);
                *(__half2*)(C2 + (size_t)(row + 8) * ldc + col) = __halves2half2(l10, l11);
            } else { // MODE 3: transposed pair: C*[col][row], ldc = M_total
                __half h00 = __float2half_rn(f00), h01 = __float2half_rn(f01);
                __half h10 = __float2half_rn(f10), h11 = __float2half_rn(f11);
                C1[(size_t)col * ldc + row]           = h00;
                C1[(size_t)(col + 1) * ldc + row]     = h01;
                C1[(size_t)col * ldc + row + 8]       = h10;
                C1[(size_t)(col + 1) * ldc + row + 8] = h11;
                C2[(size_t)col * ldc + row]           = __float2half_rn(f00 - __half2float(h00));
                C2[(size_t)(col + 1) * ldc + row]     = __float2half_rn(f01 - __half2float(h01));
                C2[(size_t)col * ldc + row + 8]       = __float2half_rn(f10 - __half2float(h10));
                C2[(size_t)(col + 1) * ldc + row + 8] = __float2half_rn(f11 - __half2float(h11));
            }
        }
    }
}

// ---------------- fp32 -> fp16 single convert -------------------------------
__global__ void __launch_bounds__(256) conv_half_kernel(
    const float* __restrict__ in, __half* __restrict__ out, int n4)
{
    int i = blockIdx.x * 256 + threadIdx.x;
    if (i >= n4) return;
    float4 v = ((const float4*)in)[i];
    ((__half2*)out)[2 * i]     = __halves2half2(__float2half_rn(v.x), __float2half_rn(v.y));
    ((__half2*)out)[2 * i + 1] = __halves2half2(__float2half_rn(v.z), __float2half_rn(v.w));
}

// ---------------- fp32 -> (hi,lo) fp16 pair split ---------------------------
__global__ void __launch_bounds__(256) split_pair_kernel(
    const float* __restrict__ in, __half* __restrict__ hi,
    __half* __restrict__ lo, int n4)
{
    int i = blockIdx.x * 256 + threadIdx.x;
    if (i >= n4) return;
    float4 v = ((const float4*)in)[i];
    __half h0 = __float2half_rn(v.x), h1 = __float2half_rn(v.y);
    __half h2 = __float2half_rn(v.z), h3 = __float2half_rn(v.w);
    __half l0 = __float2half_rn(v.x - __half2float(h0));
    __half l1 = __float2half_rn(v.y - __half2float(h1));
    __half l2 = __float2half_rn(v.z - __half2float(h2));
    __half l3 = __float2half_rn(v.w - __half2float(h3));
    ((__half2*)hi)[2 * i]     = __halves2half2(h0, h1);
    ((__half2*)hi)[2 * i + 1] = __halves2half2(h2, h3);
    ((__half2*)lo)[2 * i]     = __halves2half2(l0, l1);
    ((__half2*)lo)[2 * i + 1] = __halves2half2(l2, l3);
}

// ---------------- row softmax -> fp16 Ph ------------------------------------
__global__ void __launch_bounds__(256) softmax_h_kernel(
    const float* __restrict__ S, __half* __restrict__ Ph)
{
    __shared__ float red[8];
    const int row = blockIdx.x;
    const int t   = threadIdx.x;
    const float* p = S + (size_t)row * SEQ;

    float4 v[4];
#pragma unroll
    for (int i = 0; i < 4; i++)
        v[i] = *(const float4*)(p + 4 * (t + 256 * i));

    float mx = -INFINITY;
#pragma unroll
    for (int i = 0; i < 4; i++)
        mx = fmaxf(mx, fmaxf(fmaxf(v[i].x, v[i].y), fmaxf(v[i].z, v[i].w)));
#pragma unroll
    for (int o = 16; o > 0; o >>= 1)
        mx = fmaxf(mx, __shfl_xor_sync(0xFFFFFFFFu, mx, o));
    if ((t & 31) == 0) red[t >> 5] = mx;
    __syncthreads();
    {
        float m = red[t & 7];
#pragma unroll
        for (int o = 4; o > 0; o >>= 1)
            m = fmaxf(m, __shfl_xor_sync(0xFFFFFFFFu, m, o));
        mx = m;
    }
    __syncthreads();

    float sum = 0.0f;
#pragma unroll
    for (int i = 0; i < 4; i++) {
        v[i].x = expf(v[i].x - mx); v[i].y = expf(v[i].y - mx);
        v[i].z = expf(v[i].z - mx); v[i].w = expf(v[i].w - mx);
        sum += v[i].x + v[i].y + v[i].z + v[i].w;
    }
#pragma unroll
    for (int o = 16; o > 0; o >>= 1)
        sum += __shfl_xor_sync(0xFFFFFFFFu, sum, o);
    if ((t & 31) == 0) red[t >> 5] = sum;
    __syncthreads();
    {
        float s2 = red[t & 7];
#pragma unroll
        for (int o = 4; o > 0; o >>= 1)
            s2 += __shfl_xor_sync(0xFFFFFFFFu, s2, o);
        sum = s2;
    }

    const float inv = 1.0f / sum;
#pragma unroll
    for (int i = 0; i < 4; i++) {
        size_t idx = (size_t)row * SEQ + 4 * (t + 256 * i);
        *(__half2*)(Ph + idx) = __halves2half2(
            __float2half_rn(v[i].x * inv), __float2half_rn(v[i].y * inv));
        *(__half2*)(Ph + idx + 2) = __halves2half2(
            __float2half_rn(v[i].z * inv), __float2half_rn(v[i].w * inv));
    }
}

// ---------------------------------------------------------------------------
extern "C" void kernel_launch(void* const* d_in, const int* in_sizes, int n_in,
                              void* d_out, int out_size)
{
    (void)in_sizes; (void)n_in; (void)out_size;
    const float* X  = (const float*)d_in[0];
    const float* WQ = (const float*)d_in[1];
    const float* WK = (const float*)d_in[2];
    const float* WV = (const float*)d_in[3];
    float* O = (float*)d_out;

    __half *Xh, *WQh, *WQl, *WKh, *WKl, *WVh, *WVl;
    __half *Qh, *Kh, *Kl, *Vth, *Vtl, *Ph;
    float* S;
    cudaGetSymbolAddress((void**)&Xh, g_Xh);
    cudaGetSymbolAddress((void**)&WQh, g_WQh); cudaGetSymbolAddress((void**)&WQl, g_WQl);
    cudaGetSymbolAddress((void**)&WKh, g_WKh); cudaGetSymbolAddress((void**)&WKl, g_WKl);
    cudaGetSymbolAddress((void**)&WVh, g_WVh); cudaGetSymbolAddress((void**)&WVl, g_WVl);
    cudaGetSymbolAddress((void**)&Qh, g_Qh);
    cudaGetSymbolAddress((void**)&Kh, g_Kh);   cudaGetSymbolAddress((void**)&Kl, g_Kl);
    cudaGetSymbolAddress((void**)&Vth, g_Vth); cudaGetSymbolAddress((void**)&Vtl, g_Vtl);
    cudaGetSymbolAddress((void**)&Ph, g_Ph);
    cudaGetSymbolAddress((void**)&S, g_S);

    cudaFuncSetAttribute(gemm_2t<0>, cudaFuncAttributeMaxDynamicSharedMemorySize, GEMM_SMEM);
    cudaFuncSetAttribute(gemm_2t<1>, cudaFuncAttributeMaxDynamicSharedMemorySize, GEMM_SMEM);
    cudaFuncSetAttribute(gemm_2t<2>, cudaFuncAttributeMaxDynamicSharedMemorySize, GEMM_SMEM);
    cudaFuncSetAttribute(gemm_2t<3>, cudaFuncAttributeMaxDynamicSharedMemorySize, GEMM_SMEM);

    // 1) input conversions
    {
        int n4 = SEQ * EMB / 4;
        conv_half_kernel<<<(n4 + 255) / 256, 256>>>(X, Xh, n4);
        int w4 = OUTD * EMB / 4;
        split_pair_kernel<<<(w4 + 255) / 256, 256>>>(WQ, WQh, WQl, w4);
        split_pair_kernel<<<(w4 + 255) / 256, 256>>>(WK, WKh, WKl, w4);
        split_pair_kernel<<<(w4 + 255) / 256, 256>>>(WV, WVh, WVl, w4);
    }

    dim3 thr(NTHR);

    // 2) projections: Q single fp16; K pair; V pair transposed
    dim3 gp(OUTD / BN, SEQ / BM);
    gemm_2t<1><<<gp, thr, GEMM_SMEM>>>(Xh, WQh, WQl, nullptr, Qh, nullptr, EMB, OUTD, 1.0f);
    gemm_2t<2><<<gp, thr, GEMM_SMEM>>>(Xh, WKh, WKl, nullptr, Kh, Kl, EMB, OUTD, 1.0f);
    gemm_2t<3><<<gp, thr, GEMM_SMEM>>>(Xh, WVh, WVl, nullptr, Vth, Vtl, EMB, SEQ, 1.0f);

    // 3) scores: S = (Q @ K^T) / 32
    dim3 gs(SEQ / BN, SEQ / BM);
    gemm_2t<0><<<gs, thr, GEMM_SMEM>>>(Qh, Kh, Kl, S, nullptr, nullptr, OUTD, SEQ, 0.03125f);

    // 4) softmax -> fp16 Ph
    softmax_h_kernel<<<SEQ, 256>>>(S, Ph);

    // 5) O = P @ V, B = V^T pair
    dim3 go(OUTD / BN, SEQ / BM);
    gemm_2t<0><<<go, thr, GEMM_SMEM>>>(Ph, Vth, Vtl, O, nullptr, nullptr, SEQ, OUTD, 1.0f);
}

// round 10
// speedup vs baseline: 6.7775x; 1.6547x over previous
#include <cuda_runtime.h>
#include <cuda_fp16.h>
#include <stdint.h>
#include <stddef.h>
#include <math.h>

#define SEQ 4096
#define EMB 1024
#define OUTD 1024

// ---------------- scratch (__device__ globals; allocation-free rule) -------
__device__ __half g_Xh[(size_t)SEQ * EMB];
__device__ __half g_WQh[(size_t)OUTD * EMB];
__device__ __half g_WKh[(size_t)OUTD * EMB];
__device__ __half g_WVh[(size_t)OUTD * EMB];
__device__ __half g_Qh[(size_t)SEQ * OUTD];
__device__ __half g_Kh[(size_t)SEQ * OUTD];
__device__ __half g_Vth[(size_t)OUTD * SEQ];          // V^T
__device__ float  g_S[(size_t)SEQ * SEQ];
__device__ __half g_Ph[(size_t)SEQ * SEQ];

// ---------------- PTX helpers ----------------------------------------------
__device__ __forceinline__ uint32_t smem_u32(const void* p) {
    uint32_t a;
    asm("{ .reg .u64 t; cvta.to.shared.u64 t, %1; cvt.u32.u64 %0, t; }"
        : "=r"(a) : "l"(p));
    return a;
}
__device__ __forceinline__ void cp16(uint32_t dst, const void* src) {
    asm volatile("cp.async.cg.shared.global [%0], [%1], 16;" :: "r"(dst), "l"(src));
}
__device__ __forceinline__ void cp_commit() {
    asm volatile("cp.async.commit_group;" ::: "memory");
}
__device__ __forceinline__ void cp_wait2() {
    asm volatile("cp.async.wait_group 2;" ::: "memory");
}
__device__ __forceinline__ void ldsm4(uint32_t& r0, uint32_t& r1, uint32_t& r2,
                                      uint32_t& r3, uint32_t addr) {
    asm volatile("ldmatrix.sync.aligned.m8n8.x4.shared.b16 {%0,%1,%2,%3}, [%4];"
                 : "=r"(r0), "=r"(r1), "=r"(r2), "=r"(r3) : "r"(addr));
}
__device__ __forceinline__ void mma16816(float* c, const uint32_t* a,
                                         const uint32_t* b) {
    asm volatile(
        "mma.sync.aligned.m16n8k16.row.col.f32.f16.f16.f32 "
        "{%0,%1,%2,%3}, {%4,%5,%6,%7}, {%8,%9}, {%0,%1,%2,%3};"
        : "+f"(c[0]), "+f"(c[1]), "+f"(c[2]), "+f"(c[3])
        : "r"(a[0]), "r"(a[1]), "r"(a[2]), "r"(a[3]), "r"(b[0]), "r"(b[1]));
}

// ---------------- plain fp16 warp-MMA GEMM ---------------------------------
// C[M,N] = alpha * A[M,K] @ B[N,K]^T, fp16 A and B, K-major rows.
// CTA 256x128, BK=64, 3 cp.async stages, 16 warps (4M x 4N), warp tile 64x32.
// MODE 0: fp32 C. MODE 1: fp16 C1. MODE 2: fp16 transposed (C*[col][row]).
#define BM 256
#define BN 128
#define BK 64
#define NTHR 512

#define OFF_A 0u
#define OFF_B 32768u
#define STG   49152u
#define GEMM_SMEM (3 * 49152)

template <int MODE>
__global__ void __launch_bounds__(NTHR, 1) gemm_h(
    const __half* __restrict__ A, const __half* __restrict__ B,
    float* __restrict__ Cf, __half* __restrict__ C1,
    int K, int ldc, float alpha)
{
    extern __shared__ char smem_raw[];
    const uint32_t SBASE = smem_u32(smem_raw);

    const int t    = threadIdx.x;
    const int w    = t >> 5;
    const int lane = t & 31;
    const int m0   = blockIdx.y * BM;
    const int n0   = blockIdx.x * BN;
    const int warp_m = (w >> 2) * 64;   // 0..192
    const int warp_n = (w & 3) * 32;    // 0..96

    float acc[4][4][4];
#pragma unroll
    for (int i = 0; i < 4; i++)
#pragma unroll
        for (int j = 0; j < 4; j++)
#pragma unroll
            for (int q = 0; q < 4; q++) acc[i][j][q] = 0.0f;

    // ---- cp.async plan: 6 x 16B chunks per thread per stage ----
    const int trow = t >> 3;             // 0..63
    const int tc8  = t & 7;              // 0..7
    const uint32_t swc = (uint32_t)tc8 * 16;
    const __half* pA = A + (size_t)m0 * K;
    const __half* pB = B + (size_t)n0 * K;

    auto load_stage = [&](int s, int k0) {
        const uint32_t sb = SBASE + (uint32_t)s * STG;
#pragma unroll
        for (int i = 0; i < 6; i++) {
            const bool isA = (i < 4);
            const int row0 = isA ? i * 64 : (i - 4) * 64;
            const __half* base = isA ? pA : pB;
            const uint32_t toff = isA ? OFF_A : OFF_B;
            int rl = row0 + trow;
            const __half* src = base + (size_t)rl * K + tc8 * 8 + k0;
            uint32_t off = toff + (uint32_t)rl * 128 +
                           (swc ^ (((uint32_t)rl & 7) << 4));
            cp16(sb + off, src);
        }
    };

    // ---- ldmatrix address precompute ----
    uint32_t a_off[4], a_xor[4];
#pragma unroll
    for (int mf = 0; mf < 4; mf++) {
        int rl = warp_m + mf * 16 + (lane & 15);
        a_off[mf] = (uint32_t)rl * 128;
        a_xor[mf] = ((uint32_t)rl & 7) << 4;
    }
    const uint32_t a_bc = ((uint32_t)lane >> 4) * 16;
    uint32_t b_off[2], b_xor[2];
#pragma unroll
    for (int nfp = 0; nfp < 2; nfp++) {
        int rl = warp_n + nfp * 16 + (lane & 7) + ((lane & 16) ? 8 : 0);
        b_off[nfp] = (uint32_t)rl * 128;
        b_xor[nfp] = ((uint32_t)rl & 7) << 4;
    }
    const uint32_t b_bc = (((uint32_t)lane >> 3) & 1) * 16;

    const int kt = K / BK;

    // prologue: stages 0,1
    load_stage(0, 0);   cp_commit();
    load_stage(1, BK);  cp_commit();

    for (int it = 0; it < kt; it++) {
        if (it + 2 < kt) load_stage((it + 2) % 3, (it + 2) * BK);
        cp_commit();                       // always (possibly empty group)
        cp_wait2();                        // stage `it` resident
        __syncthreads();

        const uint32_t sb = SBASE + (uint32_t)(it % 3) * STG;

#pragma unroll
        for (int ks = 0; ks < 4; ks++) {
            const uint32_t bcA = (uint32_t)ks * 32 + a_bc;
            const uint32_t bcB = (uint32_t)ks * 32 + b_bc;
            uint32_t bh[4][2];
#pragma unroll
            for (int nfp = 0; nfp < 2; nfp++) {
                uint32_t r0, r1, r2, r3;
                ldsm4(r0, r1, r2, r3, sb + OFF_B + b_off[nfp] + (bcB ^ b_xor[nfp]));
                bh[2 * nfp][0] = r0; bh[2 * nfp][1] = r1;
                bh[2 * nfp + 1][0] = r2; bh[2 * nfp + 1][1] = r3;
            }
#pragma unroll
            for (int mf = 0; mf < 4; mf++) {
                uint32_t ah[4];
                ldsm4(ah[0], ah[1], ah[2], ah[3],
                      sb + OFF_A + a_off[mf] + (bcA ^ a_xor[mf]));
#pragma unroll
                for (int nf = 0; nf < 4; nf++)
                    mma16816(acc[mf][nf], ah, bh[nf]);
            }
        }
        __syncthreads();
    }

    // ---- epilogue ----
#pragma unroll
    for (int mf = 0; mf < 4; mf++) {
#pragma unroll
        for (int nf = 0; nf < 4; nf++) {
            int row = m0 + warp_m + mf * 16 + (lane >> 2);
            int col = n0 + warp_n + nf * 8 + (lane & 3) * 2;
            float f00 = acc[mf][nf][0] * alpha;
            float f01 = acc[mf][nf][1] * alpha;
            float f10 = acc[mf][nf][2] * alpha;
            float f11 = acc[mf][nf][3] * alpha;
            if (MODE == 0) {
                *(float2*)(Cf + (size_t)row * ldc + col)       = make_float2(f00, f01);
                *(float2*)(Cf + (size_t)(row + 8) * ldc + col) = make_float2(f10, f11);
            } else if (MODE == 1) {
                *(__half2*)(C1 + (size_t)row * ldc + col) =
                    __halves2half2(__float2half_rn(f00), __float2half_rn(f01));
                *(__half2*)(C1 + (size_t)(row + 8) * ldc + col) =
                    __halves2half2(__float2half_rn(f10), __float2half_rn(f11));
            } else { // MODE 2: transposed single: C*[col][row], ldc = M_total
                C1[(size_t)col * ldc + row]           = __float2half_rn(f00);
                C1[(size_t)(col + 1) * ldc + row]     = __float2half_rn(f01);
                C1[(size_t)col * ldc + row + 8]       = __float2half_rn(f10);
                C1[(size_t)(col + 1) * ldc + row + 8] = __float2half_rn(f11);
            }
        }
    }
}

// ---------------- fp32 -> fp16 convert --------------------------------------
__global__ void __launch_bounds__(256) conv_half_kernel(
    const float* __restrict__ in, __half* __restrict__ out, int n4)
{
    int i = blockIdx.x * 256 + threadIdx.x;
    if (i >= n4) return;
    float4 v = ((const float4*)in)[i];
    ((__half2*)out)[2 * i]     = __halves2half2(__float2half_rn(v.x), __float2half_rn(v.y));
    ((__half2*)out)[2 * i + 1] = __halves2half2(__float2half_rn(v.z), __float2half_rn(v.w));
}

// ---------------- row softmax -> fp16 Ph ------------------------------------
__global__ void __launch_bounds__(256) softmax_h_kernel(
    const float* __restrict__ S, __half* __restrict__ Ph)
{
    __shared__ float red[8];
    const int row = blockIdx.x;
    const int t   = threadIdx.x;
    const float* p = S + (size_t)row * SEQ;

    float4 v[4];
#pragma unroll
    for (int i = 0; i < 4; i++)
        v[i] = *(const float4*)(p + 4 * (t + 256 * i));

    float mx = -INFINITY;
#pragma unroll
    for (int i = 0; i < 4; i++)
        mx = fmaxf(mx, fmaxf(fmaxf(v[i].x, v[i].y), fmaxf(v[i].z, v[i].w)));
#pragma unroll
    for (int o = 16; o > 0; o >>= 1)
        mx = fmaxf(mx, __shfl_xor_sync(0xFFFFFFFFu, mx, o));
    if ((t & 31) == 0) red[t >> 5] = mx;
    __syncthreads();
    {
        float m = red[t & 7];
#pragma unroll
        for (int o = 4; o > 0; o >>= 1)
            m = fmaxf(m, __shfl_xor_sync(0xFFFFFFFFu, m, o));
        mx = m;
    }
    __syncthreads();

    float sum = 0.0f;
#pragma unroll
    for (int i = 0; i < 4; i++) {
        v[i].x = expf(v[i].x - mx); v[i].y = expf(v[i].y - mx);
        v[i].z = expf(v[i].z - mx); v[i].w = expf(v[i].w - mx);
        sum += v[i].x + v[i].y + v[i].z + v[i].w;
    }
#pragma unroll
    for (int o = 16; o > 0; o >>= 1)
        sum += __shfl_xor_sync(0xFFFFFFFFu, sum, o);
    if ((t & 31) == 0) red[t >> 5] = sum;
    __syncthreads();
    {
        float s2 = red[t & 7];
#pragma unroll
        for (int o = 4; o > 0; o >>= 1)
            s2 += __shfl_xor_sync(0xFFFFFFFFu, s2, o);
        sum = s2;
    }

    const float inv = 1.0f / sum;
#pragma unroll
    for (int i = 0; i < 4; i++) {
        size_t idx = (size_t)row * SEQ + 4 * (t + 256 * i);
        *(__half2*)(Ph + idx) = __halves2half2(
            __float2half_rn(v[i].x * inv), __float2half_rn(v[i].y * inv));
        *(__half2*)(Ph + idx + 2) = __halves2half2(
            __float2half_rn(v[i].z * inv), __float2half_rn(v[i].w * inv));
    }
}

// ---------------------------------------------------------------------------
extern "C" void kernel_launch(void* const* d_in, const int* in_sizes, int n_in,
                              void* d_out, int out_size)
{
    (void)in_sizes; (void)n_in; (void)out_size;
    const float* X  = (const float*)d_in[0];
    const float* WQ = (const float*)d_in[1];
    const float* WK = (const float*)d_in[2];
    const float* WV = (const float*)d_in[3];
    float* O = (float*)d_out;

    __half *Xh, *WQh, *WKh, *WVh, *Qh, *Kh, *Vth, *Ph;
    float* S;
    cudaGetSymbolAddress((void**)&Xh, g_Xh);
    cudaGetSymbolAddress((void**)&WQh, g_WQh);
    cudaGetSymbolAddress((void**)&WKh, g_WKh);
    cudaGetSymbolAddress((void**)&WVh, g_WVh);
    cudaGetSymbolAddress((void**)&Qh, g_Qh);
    cudaGetSymbolAddress((void**)&Kh, g_Kh);
    cudaGetSymbolAddress((void**)&Vth, g_Vth);
    cudaGetSymbolAddress((void**)&Ph, g_Ph);
    cudaGetSymbolAddress((void**)&S, g_S);

    cudaFuncSetAttribute(gemm_h<0>, cudaFuncAttributeMaxDynamicSharedMemorySize, GEMM_SMEM);
    cudaFuncSetAttribute(gemm_h<1>, cudaFuncAttributeMaxDynamicSharedMemorySize, GEMM_SMEM);
    cudaFuncSetAttribute(gemm_h<2>, cudaFuncAttributeMaxDynamicSharedMemorySize, GEMM_SMEM);

    // 1) fp32 -> fp16 conversions
    {
        int n4 = SEQ * EMB / 4;
        conv_half_kernel<<<(n4 + 255) / 256, 256>>>(X, Xh, n4);
        int w4 = OUTD * EMB / 4;
        conv_half_kernel<<<(w4 + 255) / 256, 256>>>(WQ, WQh, w4);
        conv_half_kernel<<<(w4 + 255) / 256, 256>>>(WK, WKh, w4);
        conv_half_kernel<<<(w4 + 255) / 256, 256>>>(WV, WVh, w4);
    }

    dim3 thr(NTHR);

    // 2) projections (NT): Q, K fp16; V fp16 transposed
    dim3 gp(OUTD / BN, SEQ / BM);
    gemm_h<1><<<gp, thr, GEMM_SMEM>>>(Xh, WQh, nullptr, Qh, EMB, OUTD, 1.0f);
    gemm_h<1><<<gp, thr, GEMM_SMEM>>>(Xh, WKh, nullptr, Kh, EMB, OUTD, 1.0f);
    gemm_h<2><<<gp, thr, GEMM_SMEM>>>(Xh, WVh, nullptr, Vth, EMB, SEQ, 1.0f);

    // 3) scores: S = (Q @ K^T) / 32
    dim3 gs(SEQ / BN, SEQ / BM);
    gemm_h<0><<<gs, thr, GEMM_SMEM>>>(Qh, Kh, S, nullptr, OUTD, SEQ, 0.03125f);

    // 4) softmax -> fp16 Ph
    softmax_h_kernel<<<SEQ, 256>>>(S, Ph);

    // 5) O = P @ V (B = V^T)
    dim3 go(OUTD / BN, SEQ / BM);
    gemm_h<0><<<go, thr, GEMM_SMEM>>>(Ph, Vth, O, nullptr, SEQ, OUTD, 1.0f);
}